// round 4
// baseline (speedup 1.0000x reference)
#include <cuda_runtime.h>
#include <cstdint>

#define Bn 16
#define Nn 4096
#define Sn 1024
#define Kn 32
#define Pn (Bn*Sn*Kn)   // 524288 positions
#define R2 0.01f

// ---------------- scratch (no allocations allowed) ----------------
__device__ float g_newxyz[Bn*Sn*3];
__device__ int   g_ball[Bn*Sn*Kn];
__device__ float g_PT[(size_t)Bn*Nn*68];          // [b][n][68]: xyz(3) + points(64) + pad
__device__ float g_A1[(size_t)64*Pn];
__device__ float g_A2[(size_t)64*Pn];
__device__ float g_p1[(size_t)8192*128];
__device__ float g_p2[(size_t)8192*128];
__device__ float g_scale[128];
__device__ float g_shift[128];

// ---------------- FPS ----------------
// one block per batch; 1024 threads x 4 points in registers.
// Matches JAX: dist = ((dx*dx)+(dy*dy))+(dz*dz), all round-to-nearest, no FMA;
// argmax tie-break = lowest index; idx[0]=0.
__global__ void fps_kernel(const float* __restrict__ xyz, float* __restrict__ out)
{
    extern __shared__ float sm[];
    float* sx = sm;
    float* sy = sm + Nn;
    float* sz = sm + 2*Nn;
    int*   sidx = (int*)(sm + 3*Nn);        // 1024
    float* rv  = sm + 3*Nn + Sn;            // 32
    int*   ri  = (int*)(sm + 3*Nn + Sn + 32);
    int*   sf  = (int*)(sm + 3*Nn + Sn + 64);

    int b = blockIdx.x, t = threadIdx.x;
    const float* xb = xyz + (size_t)b*3*Nn;
    for (int i = t; i < Nn; i += 1024) {
        sx[i] = xb[i]; sy[i] = xb[Nn+i]; sz[i] = xb[2*Nn+i];
    }
    __syncthreads();

    float px[4], py[4], pz[4], dm[4];
#pragma unroll
    for (int i = 0; i < 4; i++) {
        int n = t + i*1024;
        px[i]=sx[n]; py[i]=sy[n]; pz[i]=sz[n]; dm[i]=1e10f;
    }
    if (t == 0) sidx[0] = 0;
    int fcur = 0;

    for (int it = 1; it < Sn; it++) {
        float cx = sx[fcur], cy = sy[fcur], cz = sz[fcur];
        float bv = -1.f; int bi = 1<<30;
#pragma unroll
        for (int i = 0; i < 4; i++) {
            float dx = __fadd_rn(px[i], -cx);
            float dy = __fadd_rn(py[i], -cy);
            float dz = __fadd_rn(pz[i], -cz);
            float d  = __fadd_rn(__fadd_rn(__fmul_rn(dx,dx), __fmul_rn(dy,dy)), __fmul_rn(dz,dz));
            float nd = fminf(dm[i], d);
            dm[i] = nd;
            int n = t + i*1024;
            if (nd > bv || (nd == bv && n < bi)) { bv = nd; bi = n; }
        }
#pragma unroll
        for (int o = 16; o; o >>= 1) {
            float ov = __shfl_down_sync(0xffffffffu, bv, o);
            int   oi = __shfl_down_sync(0xffffffffu, bi, o);
            if (ov > bv || (ov == bv && oi < bi)) { bv = ov; bi = oi; }
        }
        if ((t & 31) == 0) { rv[t>>5] = bv; ri[t>>5] = bi; }
        __syncthreads();
        if (t < 32) {
            bv = rv[t]; bi = ri[t];
#pragma unroll
            for (int o = 16; o; o >>= 1) {
                float ov = __shfl_down_sync(0xffffffffu, bv, o);
                int   oi = __shfl_down_sync(0xffffffffu, bi, o);
                if (ov > bv || (ov == bv && oi < bi)) { bv = ov; bi = oi; }
            }
            if (t == 0) { sf[0] = bi; sidx[it] = bi; }
        }
        __syncthreads();
        fcur = sf[0];
    }

    // outputs: new_xyz (B,3,S) into d_out head + centered-group helper buffer
    {
        int n = sidx[t];
        float x = sx[n], y = sy[n], z = sz[n];
        g_newxyz[(b*Sn+t)*3+0] = x;
        g_newxyz[(b*Sn+t)*3+1] = y;
        g_newxyz[(b*Sn+t)*3+2] = z;
        out[((size_t)b*3+0)*Sn + t] = x;
        out[((size_t)b*3+1)*Sn + t] = y;
        out[((size_t)b*3+2)*Sn + t] = z;
    }
}

// ---------------- ball query ----------------
// one warp per centroid, 8 centroids per 256-thread block.
// sqrdist via the reference's expanded formula; collect first 32 indices
// ascending; pad with first hit.
__global__ void ball_kernel(const float* __restrict__ xyz)
{
    extern __shared__ float bsm[];
    float* sx = bsm;
    float* sy = bsm + Nn;
    float* sz = bsm + 2*Nn;
    float* sn = bsm + 3*Nn;

    int b = blockIdx.y, t = threadIdx.x;
    const float* xb = xyz + (size_t)b*3*Nn;
    for (int i = t; i < Nn; i += 256) {
        float x = xb[i], y = xb[Nn+i], z = xb[2*Nn+i];
        sx[i]=x; sy[i]=y; sz[i]=z;
        sn[i] = __fadd_rn(__fadd_rn(__fmul_rn(x,x), __fmul_rn(y,y)), __fmul_rn(z,z));
    }
    __syncthreads();

    int w = t >> 5, lane = t & 31;
    int s = blockIdx.x*8 + w;
    const float* ctr = &g_newxyz[(b*Sn+s)*3];
    float cx = ctr[0], cy = ctr[1], cz = ctr[2];
    float cn = __fadd_rn(__fadd_rn(__fmul_rn(cx,cx), __fmul_rn(cy,cy)), __fmul_rn(cz,cz));

    int* dst = &g_ball[((size_t)b*Sn+s)*Kn];
    int cnt = 0, first = -1;
    for (int j = 0; j < Nn/32; j++) {
        int n = j*32 + lane;
        float dot = __fadd_rn(__fadd_rn(__fmul_rn(sx[n],cx), __fmul_rn(sy[n],cy)), __fmul_rn(sz[n],cz));
        float d = __fadd_rn(__fadd_rn(__fmul_rn(-2.f,dot), cn), sn[n]);
        bool in = !(d > R2);
        unsigned m = __ballot_sync(0xffffffffu, in);
        if (m) {
            if (first < 0) first = j*32 + __ffs(m) - 1;
            if (in) {
                int pos = cnt + __popc(m & ((1u<<lane)-1u));
                if (pos < Kn) dst[pos] = n;
            }
            cnt += __popc(m);
            if (cnt >= Kn) break;
        }
    }
    for (int pos = cnt + lane; pos < Kn; pos += 32) dst[pos] = first;
}

// ---------------- point table transpose ----------------
__global__ void build_pt(const float* __restrict__ xyz, const float* __restrict__ pts)
{
    int i = blockIdx.x*256 + threadIdx.x;      // i = b*4096 + n, grid covers exactly
    int b = i >> 12, n = i & 4095;
    float* dst = &g_PT[(size_t)i*68];
    dst[0] = xyz[((size_t)b*3+0)*Nn + n];
    dst[1] = xyz[((size_t)b*3+1)*Nn + n];
    dst[2] = xyz[((size_t)b*3+2)*Nn + n];
#pragma unroll 4
    for (int c = 0; c < 64; c++) dst[3+c] = pts[((size_t)b*64+c)*Nn + n];
    dst[67] = 0.f;
}

// ---------------- shared stats reduction helper ----------------
template<int COUT, int CPT>
__device__ __forceinline__ void stats_reduce(float* red1, float* red2,
                                             float (&acc)[CPT], int co0)
{
    int t = threadIdx.x, lane = t & 31, w = t >> 5;
    for (int i = t; i < COUT*8; i += 256) { red1[i] = 0.f; red2[i] = 0.f; }
    __syncthreads();
#pragma unroll
    for (int j = 0; j < CPT; j++) {
        float s1 = acc[j], s2 = acc[j]*acc[j];
#pragma unroll
        for (int o = 16; o; o >>= 1) {
            s1 += __shfl_down_sync(0xffffffffu, s1, o);
            s2 += __shfl_down_sync(0xffffffffu, s2, o);
        }
        if (lane == 0) { red1[(co0+j)*8 + w] = s1; red2[(co0+j)*8 + w] = s2; }
    }
    __syncthreads();
    for (int co = t; co < COUT; co += 256) {
        float a = 0.f, bb = 0.f;
#pragma unroll
        for (int w2 = 0; w2 < 8; w2++) { a += red1[co*8+w2]; bb += red2[co*8+w2]; }
        g_p1[(size_t)blockIdx.x*COUT + co] = a;
        g_p2[(size_t)blockIdx.x*COUT + co] = bb;
    }
}

// ---------------- layer 1: gather + conv (67->64), center folded into init ----------------
template<int MODE>   // 0 = stats, 1 = apply(BN+ReLU -> A1)
__global__ __launch_bounds__(256, 2) void conv1_kernel(const float* __restrict__ W0,
                                                       const float* __restrict__ b0)
{
    __shared__ float Ws[64*68];
    __shared__ float red1[64*8], red2[64*8];
    int t = threadIdx.x;
    for (int i = t; i < 64*68; i += 256) {
        int o = i/68, c = i%68;
        Ws[i] = (c < 67) ? W0[o*67 + c] : 0.f;
    }
    __syncthreads();

    int p  = blockIdx.x*256 + t;
    int n  = g_ball[p];
    int b  = p >> 15;                 // /(Sn*Kn)
    int sg = p >> 5;                  // global centroid id
    float cx = g_newxyz[sg*3], cy = g_newxyz[sg*3+1], cz = g_newxyz[sg*3+2];
    const float4* row = (const float4*)&g_PT[((size_t)(b<<12) + (size_t)n)*68];

    float acc[64];
#pragma unroll
    for (int j = 0; j < 64; j++)
        acc[j] = b0[j] - (Ws[j*68]*cx + Ws[j*68+1]*cy + Ws[j*68+2]*cz);

#pragma unroll 1
    for (int cc = 0; cc < 17; cc++) {
        float4 v = row[cc];
#pragma unroll
        for (int j = 0; j < 64; j++) {
            const float* wr = &Ws[j*68 + cc*4];
            acc[j] = fmaf(v.x, wr[0], acc[j]);
            acc[j] = fmaf(v.y, wr[1], acc[j]);
            acc[j] = fmaf(v.z, wr[2], acc[j]);
            acc[j] = fmaf(v.w, wr[3], acc[j]);
        }
    }

    if (MODE == 1) {
#pragma unroll
        for (int j = 0; j < 64; j++) {
            float y = fmaf(acc[j], g_scale[j], g_shift[j]);
            g_A1[(size_t)j*Pn + p] = fmaxf(y, 0.f);
        }
    } else {
        stats_reduce<64,64>(red1, red2, acc, 0);
    }
}

// ---------------- generic conv layers 2/3 ----------------
template<int CIN, int COUT, int CPT, int MODE, bool POOL>
__global__ __launch_bounds__(256, 2) void convN_kernel(const float* __restrict__ A,
                                                       const float* __restrict__ Wg,
                                                       const float* __restrict__ bg,
                                                       float* __restrict__ Aout,
                                                       float* __restrict__ outpts)
{
    constexpr int G   = COUT / CPT;
    constexpr int PPB = 256 / G;
    __shared__ float Ws[COUT*CIN];
    __shared__ float red1[COUT*8], red2[COUT*8];
    int t = threadIdx.x;
    for (int i = t; i < COUT*CIN; i += 256) Ws[i] = Wg[i];
    __syncthreads();

    int pl = t % PPB, grp = t / PPB, co0 = grp*CPT;
    int p = blockIdx.x*PPB + pl;

    float acc[CPT];
#pragma unroll
    for (int j = 0; j < CPT; j++) acc[j] = bg[co0+j];

#pragma unroll 4
    for (int c = 0; c < CIN; c++) {
        float x = A[(size_t)c*Pn + p];
#pragma unroll
        for (int j = 0; j < CPT; j++)
            acc[j] = fmaf(x, Ws[(co0+j)*CIN + c], acc[j]);
    }

    if (MODE == 0) {
        stats_reduce<COUT,CPT>(red1, red2, acc, co0);
        return;
    }
    if (!POOL) {
#pragma unroll
        for (int j = 0; j < CPT; j++) {
            float y = fmaf(acc[j], g_scale[co0+j], g_shift[co0+j]);
            Aout[(size_t)(co0+j)*Pn + p] = fmaxf(y, 0.f);
        }
    } else {
        int lane = t & 31;
        int sg = p >> 5;
        int bb = sg >> 10, s = sg & 1023;
#pragma unroll
        for (int j = 0; j < CPT; j++) {
            float y = fmaf(acc[j], g_scale[co0+j], g_shift[co0+j]);
            y = fmaxf(y, 0.f);
#pragma unroll
            for (int o = 16; o; o >>= 1)
                y = fmaxf(y, __shfl_xor_sync(0xffffffffu, y, o));
            if (lane == j)
                outpts[((size_t)(bb*128 + co0 + j))*Sn + s] = y;
        }
    }
}

// ---------------- stats -> scale/shift ----------------
__global__ void reduce_stats_kernel(int NB, int COUT,
                                    const float* __restrict__ gamma,
                                    const float* __restrict__ beta)
{
    int co = blockIdx.x, t = threadIdx.x;
    double s1 = 0.0, s2 = 0.0;
    for (int i = t; i < NB; i += 256) {
        s1 += (double)g_p1[(size_t)i*COUT + co];
        s2 += (double)g_p2[(size_t)i*COUT + co];
    }
    __shared__ double r1[256], r2[256];
    r1[t] = s1; r2[t] = s2;
    __syncthreads();
    for (int o = 128; o; o >>= 1) {
        if (t < o) { r1[t] += r1[t+o]; r2[t] += r2[t+o]; }
        __syncthreads();
    }
    if (t == 0) {
        double mu  = r1[0] * (1.0 / Pn);
        double var = r2[0] * (1.0 / Pn) - mu*mu;
        double sc  = (double)gamma[co] / sqrt(var + 1e-5);
        g_scale[co] = (float)sc;
        g_shift[co] = (float)((double)beta[co] - mu*sc);
    }
}

// ---------------- launch ----------------
extern "C" void kernel_launch(void* const* d_in, const int* in_sizes, int n_in,
                              void* d_out, int out_size)
{
    const float* xyz = (const float*)d_in[0];
    const float* pts = (const float*)d_in[1];
    const float* W0  = (const float*)d_in[2];
    const float* b0  = (const float*)d_in[3];
    const float* g0  = (const float*)d_in[4];
    const float* be0 = (const float*)d_in[5];
    const float* W1  = (const float*)d_in[6];
    const float* b1  = (const float*)d_in[7];
    const float* g1  = (const float*)d_in[8];
    const float* be1 = (const float*)d_in[9];
    const float* W2  = (const float*)d_in[10];
    const float* b2  = (const float*)d_in[11];
    const float* g2  = (const float*)d_in[12];
    const float* be2 = (const float*)d_in[13];

    float* out    = (float*)d_out;
    float* outpts = out + (size_t)Bn*3*Sn;

    const int FPS_SMEM  = (3*Nn + Sn + 80) * 4;   // ~53.8 KB
    const int BALL_SMEM = 4*Nn*4;                 // 64 KB
    cudaFuncSetAttribute(fps_kernel,  cudaFuncAttributeMaxDynamicSharedMemorySize, FPS_SMEM);
    cudaFuncSetAttribute(ball_kernel, cudaFuncAttributeMaxDynamicSharedMemorySize, BALL_SMEM);

    float *pA1 = nullptr, *pA2 = nullptr;
    cudaGetSymbolAddress((void**)&pA1, g_A1);
    cudaGetSymbolAddress((void**)&pA2, g_A2);

    fps_kernel<<<Bn, 1024, FPS_SMEM>>>(xyz, out);
    ball_kernel<<<dim3(Sn/8, Bn), 256, BALL_SMEM>>>(xyz);
    build_pt<<<(Bn*Nn)/256, 256>>>(xyz, pts);

    // layer 1 (67 -> 64)
    conv1_kernel<0><<<Pn/256, 256>>>(W0, b0);
    reduce_stats_kernel<<<64, 256>>>(Pn/256, 64, g0, be0);
    conv1_kernel<1><<<Pn/256, 256>>>(W0, b0);

    // layer 2 (64 -> 64)
    convN_kernel<64,64,64,0,false><<<Pn/256, 256>>>(pA1, W1, b1, nullptr, nullptr);
    reduce_stats_kernel<<<64, 256>>>(Pn/256, 64, g1, be1);
    convN_kernel<64,64,64,1,false><<<Pn/256, 256>>>(pA1, W1, b1, pA2, nullptr);

    // layer 3 (64 -> 128) + maxpool over k
    convN_kernel<64,128,32,0,false><<<Pn/64, 256>>>(pA2, W2, b2, nullptr, nullptr);
    reduce_stats_kernel<<<128, 256>>>(Pn/64, 128, g2, be2);
    convN_kernel<64,128,32,1,true><<<Pn/64, 256>>>(pA2, W2, b2, nullptr, outpts);
}

// round 9
// speedup vs baseline: 1.6918x; 1.6918x over previous
#include <cuda_runtime.h>
#include <cstdint>

#define Bn 16
#define Nn 4096
#define Sn 1024
#define Kn 32
#define Pn (Bn*Sn*Kn)   // 524288 positions
#define Sg (Bn*Sn)      // 16384 centroids
#define R2 0.01f

// ---------------- scratch (no allocations allowed) ----------------
__device__ float g_newxyz[Bn*Sn*3];
__device__ int   g_ball[Bn*Sn*Kn];
__device__ float g_PT[(size_t)Bn*Nn*68];          // [b][n][68]: xyz(3)+points(64)+pad
__device__ float g_A1[(size_t)64*Pn];             // layer1 pre-activation
__device__ float g_A2[(size_t)64*Pn];             // layer2 pre-activation
__device__ float g_M [(size_t)128*Sg];            // layer3 pre-act k-max
__device__ float g_p1[(size_t)8192*128];
__device__ float g_p2[(size_t)8192*128];
__device__ float g_scale[3][128];
__device__ float g_shift[3][128];

// ---------------- FPS ----------------
__global__ void fps_kernel(const float* __restrict__ xyz, float* __restrict__ out)
{
    extern __shared__ float sm[];
    float* sx = sm;
    float* sy = sm + Nn;
    float* sz = sm + 2*Nn;
    int*   sidx = (int*)(sm + 3*Nn);
    float* rv  = sm + 3*Nn + Sn;
    int*   ri  = (int*)(sm + 3*Nn + Sn + 32);
    int*   sf  = (int*)(sm + 3*Nn + Sn + 64);

    int b = blockIdx.x, t = threadIdx.x;
    const float* xb = xyz + (size_t)b*3*Nn;
    for (int i = t; i < Nn; i += 1024) {
        sx[i] = xb[i]; sy[i] = xb[Nn+i]; sz[i] = xb[2*Nn+i];
    }
    __syncthreads();

    float px[4], py[4], pz[4], dm[4];
#pragma unroll
    for (int i = 0; i < 4; i++) {
        int n = t + i*1024;
        px[i]=sx[n]; py[i]=sy[n]; pz[i]=sz[n]; dm[i]=1e10f;
    }
    if (t == 0) sidx[0] = 0;
    int fcur = 0;

    for (int it = 1; it < Sn; it++) {
        float cx = sx[fcur], cy = sy[fcur], cz = sz[fcur];
        float bv = -1.f; int bi = 1<<30;
#pragma unroll
        for (int i = 0; i < 4; i++) {
            float dx = __fadd_rn(px[i], -cx);
            float dy = __fadd_rn(py[i], -cy);
            float dz = __fadd_rn(pz[i], -cz);
            float d  = __fadd_rn(__fadd_rn(__fmul_rn(dx,dx), __fmul_rn(dy,dy)), __fmul_rn(dz,dz));
            float nd = fminf(dm[i], d);
            dm[i] = nd;
            int n = t + i*1024;
            if (nd > bv || (nd == bv && n < bi)) { bv = nd; bi = n; }
        }
#pragma unroll
        for (int o = 16; o; o >>= 1) {
            float ov = __shfl_down_sync(0xffffffffu, bv, o);
            int   oi = __shfl_down_sync(0xffffffffu, bi, o);
            if (ov > bv || (ov == bv && oi < bi)) { bv = ov; bi = oi; }
        }
        if ((t & 31) == 0) { rv[t>>5] = bv; ri[t>>5] = bi; }
        __syncthreads();
        if (t < 32) {
            bv = rv[t]; bi = ri[t];
#pragma unroll
            for (int o = 16; o; o >>= 1) {
                float ov = __shfl_down_sync(0xffffffffu, bv, o);
                int   oi = __shfl_down_sync(0xffffffffu, bi, o);
                if (ov > bv || (ov == bv && oi < bi)) { bv = ov; bi = oi; }
            }
            if (t == 0) { sf[0] = bi; sidx[it] = bi; }
        }
        __syncthreads();
        fcur = sf[0];
    }
    {
        int n = sidx[t];
        float x = sx[n], y = sy[n], z = sz[n];
        g_newxyz[(b*Sn+t)*3+0] = x;
        g_newxyz[(b*Sn+t)*3+1] = y;
        g_newxyz[(b*Sn+t)*3+2] = z;
        out[((size_t)b*3+0)*Sn + t] = x;
        out[((size_t)b*3+1)*Sn + t] = y;
        out[((size_t)b*3+2)*Sn + t] = z;
    }
}

// ---------------- ball query ----------------
__global__ void ball_kernel(const float* __restrict__ xyz)
{
    extern __shared__ float bsm[];
    float* sx = bsm;
    float* sy = bsm + Nn;
    float* sz = bsm + 2*Nn;
    float* sn = bsm + 3*Nn;

    int b = blockIdx.y, t = threadIdx.x;
    const float* xb = xyz + (size_t)b*3*Nn;
    for (int i = t; i < Nn; i += 256) {
        float x = xb[i], y = xb[Nn+i], z = xb[2*Nn+i];
        sx[i]=x; sy[i]=y; sz[i]=z;
        sn[i] = __fadd_rn(__fadd_rn(__fmul_rn(x,x), __fmul_rn(y,y)), __fmul_rn(z,z));
    }
    __syncthreads();

    int w = t >> 5, lane = t & 31;
    int s = blockIdx.x*8 + w;
    const float* ctr = &g_newxyz[(b*Sn+s)*3];
    float cx = ctr[0], cy = ctr[1], cz = ctr[2];
    float cn = __fadd_rn(__fadd_rn(__fmul_rn(cx,cx), __fmul_rn(cy,cy)), __fmul_rn(cz,cz));

    int* dst = &g_ball[((size_t)b*Sn+s)*Kn];
    int cnt = 0, first = -1;
    for (int j = 0; j < Nn/32; j++) {
        int n = j*32 + lane;
        float dot = __fadd_rn(__fadd_rn(__fmul_rn(sx[n],cx), __fmul_rn(sy[n],cy)), __fmul_rn(sz[n],cz));
        float d = __fadd_rn(__fadd_rn(__fmul_rn(-2.f,dot), cn), sn[n]);
        bool in = !(d > R2);
        unsigned m = __ballot_sync(0xffffffffu, in);
        if (m) {
            if (first < 0) first = j*32 + __ffs(m) - 1;
            if (in) {
                int pos = cnt + __popc(m & ((1u<<lane)-1u));
                if (pos < Kn) dst[pos] = n;
            }
            cnt += __popc(m);
            if (cnt >= Kn) break;
        }
    }
    for (int pos = cnt + lane; pos < Kn; pos += 32) dst[pos] = first;
}

// ---------------- point table transpose ----------------
__global__ void build_pt(const float* __restrict__ xyz, const float* __restrict__ pts)
{
    int i = blockIdx.x*256 + threadIdx.x;
    int b = i >> 12, n = i & 4095;
    float* dst = &g_PT[(size_t)i*68];
    dst[0] = xyz[((size_t)b*3+0)*Nn + n];
    dst[1] = xyz[((size_t)b*3+1)*Nn + n];
    dst[2] = xyz[((size_t)b*3+2)*Nn + n];
#pragma unroll 4
    for (int c = 0; c < 64; c++) dst[3+c] = pts[((size_t)b*64+c)*Nn + n];
    dst[67] = 0.f;
}

// ---------------- stats reduction helper ----------------
// 256-thread block, CPT channel sums per thread starting at co0.
template<int COUT, int CPT>
__device__ __forceinline__ void stats_reduce2(float* red1, float* red2,
                                              float (&s1)[CPT], float (&s2)[CPT],
                                              int co0, int nbIdx)
{
    int t = threadIdx.x, lane = t & 31, w = t >> 5;
    for (int i = t; i < COUT*8; i += 256) { red1[i] = 0.f; red2[i] = 0.f; }
    __syncthreads();
#pragma unroll
    for (int j = 0; j < CPT; j++) {
        float a = s1[j], bb = s2[j];
#pragma unroll
        for (int o = 16; o; o >>= 1) {
            a  += __shfl_down_sync(0xffffffffu, a,  o);
            bb += __shfl_down_sync(0xffffffffu, bb, o);
        }
        if (lane == 0) { red1[(co0+j)*8 + w] = a; red2[(co0+j)*8 + w] = bb; }
    }
    __syncthreads();
    for (int co = t; co < COUT; co += 256) {
        float a = 0.f, bb = 0.f;
#pragma unroll
        for (int w2 = 0; w2 < 8; w2++) { a += red1[co*8+w2]; bb += red2[co*8+w2]; }
        g_p1[(size_t)nbIdx*COUT + co] = a;
        g_p2[(size_t)nbIdx*COUT + co] = bb;
    }
}

// ---------------- layer 1: gather + conv 67->64, single pass ----------------
// 256 thr: grp=t>>6 (16 channels each), pl=t&63 (4 positions each). PPB=256.
// Writes pre-activation to g_A1 and stats partials.
__global__ __launch_bounds__(256, 2) void conv1_kernel(const float* __restrict__ W0,
                                                       const float* __restrict__ b0)
{
    __shared__ float Wt[68*64];          // c-major: Wt[c*64+j]
    __shared__ float red1[64*8], red2[64*8];
    int t = threadIdx.x;
    for (int i = t; i < 68*64; i += 256) {
        int c = i >> 6, j = i & 63;
        Wt[i] = (c < 67) ? W0[j*67 + c] : 0.f;
    }
    __syncthreads();

    int grp = t >> 6, pl = t & 63, co0 = grp*16;
    int p0 = blockIdx.x*256 + pl*4;
    int b  = p0 >> 15;
    int sg = p0 >> 5;
    float cx = g_newxyz[sg*3], cy = g_newxyz[sg*3+1], cz = g_newxyz[sg*3+2];

    int4 bn = *(const int4*)&g_ball[p0];
    const float4* r0 = (const float4*)&g_PT[((size_t)(b<<12) + bn.x)*68];
    const float4* r1 = (const float4*)&g_PT[((size_t)(b<<12) + bn.y)*68];
    const float4* r2 = (const float4*)&g_PT[((size_t)(b<<12) + bn.z)*68];
    const float4* r3 = (const float4*)&g_PT[((size_t)(b<<12) + bn.w)*68];

    float acc[64];                       // [j][q] flattened j*4+q
#pragma unroll
    for (int j = 0; j < 16; j++) {
        int jg = co0 + j;
        float base = b0[jg] - (Wt[jg]*cx + Wt[64+jg]*cy + Wt[128+jg]*cz);
#pragma unroll
        for (int q = 0; q < 4; q++) acc[j*4+q] = base;
    }

    const float4* Wt4 = (const float4*)Wt;
#pragma unroll 4
    for (int cc = 0; cc < 17; cc++) {
        float4 v0 = r0[cc], v1 = r1[cc], v2 = r2[cc], v3 = r3[cc];
        const float* a0 = (const float*)&v0;
        const float* a1 = (const float*)&v1;
        const float* a2 = (const float*)&v2;
        const float* a3 = (const float*)&v3;
#pragma unroll
        for (int c4 = 0; c4 < 4; c4++) {
            int c = cc*4 + c4;
            float x0 = a0[c4], x1 = a1[c4], x2 = a2[c4], x3 = a3[c4];
            const float4* wr = Wt4 + c*16 + (co0 >> 2);
#pragma unroll
            for (int jj = 0; jj < 4; jj++) {
                float4 w = wr[jj];
                float* A = &acc[jj*16];
                A[0]  = fmaf(x0, w.x, A[0]);  A[1]  = fmaf(x1, w.x, A[1]);
                A[2]  = fmaf(x2, w.x, A[2]);  A[3]  = fmaf(x3, w.x, A[3]);
                A[4]  = fmaf(x0, w.y, A[4]);  A[5]  = fmaf(x1, w.y, A[5]);
                A[6]  = fmaf(x2, w.y, A[6]);  A[7]  = fmaf(x3, w.y, A[7]);
                A[8]  = fmaf(x0, w.z, A[8]);  A[9]  = fmaf(x1, w.z, A[9]);
                A[10] = fmaf(x2, w.z, A[10]); A[11] = fmaf(x3, w.z, A[11]);
                A[12] = fmaf(x0, w.w, A[12]); A[13] = fmaf(x1, w.w, A[13]);
                A[14] = fmaf(x2, w.w, A[14]); A[15] = fmaf(x3, w.w, A[15]);
            }
        }
    }

    // store pre-activation + build stats
    float s1[16], s2[16];
#pragma unroll
    for (int j = 0; j < 16; j++) {
        float a0 = acc[j*4+0], a1 = acc[j*4+1], a2 = acc[j*4+2], a3 = acc[j*4+3];
        float4 v = make_float4(a0, a1, a2, a3);
        *(float4*)&g_A1[(size_t)(co0+j)*Pn + p0] = v;
        s1[j] = a0+a1+a2+a3;
        s2[j] = a0*a0+a1*a1+a2*a2+a3*a3;
    }
    stats_reduce2<64,16>(red1, red2, s1, s2, co0, blockIdx.x);
}

// ---------------- layers 2/3: conv with fused input BN+ReLU ----------------
// A holds previous layer's PRE-activation; this kernel applies
// y = relu(a*scale+shift) on load. Single pass: writes pre-act (layer2) or
// k-max of pre-act (layer3, valid since scale>0) + stats partials.
template<int COUT, int LAYER, bool POOL>
__global__ __launch_bounds__(256, 2) void convN_kernel(const float* __restrict__ A,
                                                       const float* __restrict__ Wg,
                                                       const float* __restrict__ bg,
                                                       float* __restrict__ Aout)
{
    constexpr int CIN = 64;
    constexpr int CPT = 16;
    constexpr int G   = COUT / CPT;        // 4 or 8
    constexpr int PL  = 256 / G;           // 64 or 32
    constexpr int PPB = PL * 4;            // 256 or 128

    __shared__ float Wt[CIN*COUT];         // c-major
    __shared__ float red1[COUT*8], red2[COUT*8];
    __shared__ float sc[CIN], sh[CIN];

    int t = threadIdx.x;
    for (int i = t; i < CIN*COUT; i += 256) {
        int c = i / COUT, j = i % COUT;
        Wt[i] = Wg[j*CIN + c];
    }
    if (t < CIN) { sc[t] = g_scale[LAYER-1][t]; sh[t] = g_shift[LAYER-1][t]; }
    __syncthreads();

    int grp = t / PL, pl = t % PL, co0 = grp*CPT;
    int p0 = blockIdx.x*PPB + pl*4;

    float acc[64];
#pragma unroll
    for (int j = 0; j < 16; j++) {
        float base = bg[co0+j];
#pragma unroll
        for (int q = 0; q < 4; q++) acc[j*4+q] = base;
    }

    const float4* Wt4 = (const float4*)Wt;
#pragma unroll 4
    for (int c = 0; c < CIN; c++) {
        float4 v = *(const float4*)&A[(size_t)c*Pn + p0];
        float s = sc[c], h = sh[c];
        float x0 = fmaxf(fmaf(v.x, s, h), 0.f);
        float x1 = fmaxf(fmaf(v.y, s, h), 0.f);
        float x2 = fmaxf(fmaf(v.z, s, h), 0.f);
        float x3 = fmaxf(fmaf(v.w, s, h), 0.f);
        const float4* wr = Wt4 + c*(COUT/4) + (co0 >> 2);
#pragma unroll
        for (int jj = 0; jj < 4; jj++) {
            float4 w = wr[jj];
            float* Ac = &acc[jj*16];
            Ac[0]  = fmaf(x0, w.x, Ac[0]);  Ac[1]  = fmaf(x1, w.x, Ac[1]);
            Ac[2]  = fmaf(x2, w.x, Ac[2]);  Ac[3]  = fmaf(x3, w.x, Ac[3]);
            Ac[4]  = fmaf(x0, w.y, Ac[4]);  Ac[5]  = fmaf(x1, w.y, Ac[5]);
            Ac[6]  = fmaf(x2, w.y, Ac[6]);  Ac[7]  = fmaf(x3, w.y, Ac[7]);
            Ac[8]  = fmaf(x0, w.z, Ac[8]);  Ac[9]  = fmaf(x1, w.z, Ac[9]);
            Ac[10] = fmaf(x2, w.z, Ac[10]); Ac[11] = fmaf(x3, w.z, Ac[11]);
            Ac[12] = fmaf(x0, w.w, Ac[12]); Ac[13] = fmaf(x1, w.w, Ac[13]);
            Ac[14] = fmaf(x2, w.w, Ac[14]); Ac[15] = fmaf(x3, w.w, Ac[15]);
        }
    }

    float s1[16], s2[16];
#pragma unroll
    for (int j = 0; j < 16; j++) {
        float a0 = acc[j*4+0], a1 = acc[j*4+1], a2 = acc[j*4+2], a3 = acc[j*4+3];
        s1[j] = a0+a1+a2+a3;
        s2[j] = a0*a0+a1*a1+a2*a2+a3*a3;
        if (!POOL) {
            *(float4*)&Aout[(size_t)(co0+j)*Pn + p0] = make_float4(a0,a1,a2,a3);
        }
    }
    if (POOL) {
        // k-max over pre-act: thread covers 4 k of one centroid; 8 lanes share
        // a centroid (pl>>3). scale>0 => relu(BN(max)) == max(relu(BN(.))).
        int lane = t & 31;
        int sgG = blockIdx.x*(PPB/32) + (pl >> 3);
#pragma unroll
        for (int j = 0; j < 16; j++) {
            float m = fmaxf(fmaxf(acc[j*4+0], acc[j*4+1]),
                            fmaxf(acc[j*4+2], acc[j*4+3]));
            m = fmaxf(m, __shfl_xor_sync(0xffffffffu, m, 1));
            m = fmaxf(m, __shfl_xor_sync(0xffffffffu, m, 2));
            m = fmaxf(m, __shfl_xor_sync(0xffffffffu, m, 4));
            if ((j & 7) == (lane & 7))
                g_M[(size_t)(co0+j)*Sg + sgG] = m;
        }
    }
    stats_reduce2<COUT,16>(red1, red2, s1, s2, co0, blockIdx.x);
}

// ---------------- stats -> scale/shift ----------------
__global__ void reduce_stats_kernel(int NB, int COUT, int layer,
                                    const float* __restrict__ gamma,
                                    const float* __restrict__ beta)
{
    int co = blockIdx.x, t = threadIdx.x;
    double s1 = 0.0, s2 = 0.0;
    for (int i = t; i < NB; i += 256) {
        s1 += (double)g_p1[(size_t)i*COUT + co];
        s2 += (double)g_p2[(size_t)i*COUT + co];
    }
    __shared__ double r1[256], r2[256];
    r1[t] = s1; r2[t] = s2;
    __syncthreads();
    for (int o = 128; o; o >>= 1) {
        if (t < o) { r1[t] += r1[t+o]; r2[t] += r2[t+o]; }
        __syncthreads();
    }
    if (t == 0) {
        double mu  = r1[0] * (1.0 / Pn);
        double var = r2[0] * (1.0 / Pn) - mu*mu;
        double scd = (double)gamma[co] / sqrt(var + 1e-5);
        g_scale[layer][co] = (float)scd;
        g_shift[layer][co] = (float)((double)beta[co] - mu*scd);
    }
}

// ---------------- finalize: BN3+ReLU on pooled pre-act max ----------------
__global__ void finalize_kernel(float* __restrict__ outpts)
{
    int i = blockIdx.x*256 + threadIdx.x;      // 128*16384 = 2M
    int co = i >> 14, sg = i & 16383;
    float y = fmaf(g_M[i], g_scale[2][co], g_shift[2][co]);
    y = fmaxf(y, 0.f);
    int b = sg >> 10, s = sg & 1023;
    outpts[((size_t)(b*128 + co))*1024 + s] = y;
}

// ---------------- launch ----------------
extern "C" void kernel_launch(void* const* d_in, const int* in_sizes, int n_in,
                              void* d_out, int out_size)
{
    const float* xyz = (const float*)d_in[0];
    const float* pts = (const float*)d_in[1];
    const float* W0  = (const float*)d_in[2];
    const float* b0  = (const float*)d_in[3];
    const float* g0  = (const float*)d_in[4];
    const float* be0 = (const float*)d_in[5];
    const float* W1  = (const float*)d_in[6];
    const float* b1  = (const float*)d_in[7];
    const float* g1  = (const float*)d_in[8];
    const float* be1 = (const float*)d_in[9];
    const float* W2  = (const float*)d_in[10];
    const float* b2  = (const float*)d_in[11];
    const float* g2  = (const float*)d_in[12];
    const float* be2 = (const float*)d_in[13];

    float* out    = (float*)d_out;
    float* outpts = out + (size_t)Bn*3*Sn;

    const int FPS_SMEM  = (3*Nn + Sn + 80) * 4;
    const int BALL_SMEM = 4*Nn*4;
    cudaFuncSetAttribute(fps_kernel,  cudaFuncAttributeMaxDynamicSharedMemorySize, FPS_SMEM);
    cudaFuncSetAttribute(ball_kernel, cudaFuncAttributeMaxDynamicSharedMemorySize, BALL_SMEM);

    float *pA1 = nullptr, *pA2 = nullptr;
    cudaGetSymbolAddress((void**)&pA1, g_A1);
    cudaGetSymbolAddress((void**)&pA2, g_A2);

    fps_kernel<<<Bn, 1024, FPS_SMEM>>>(xyz, out);
    ball_kernel<<<dim3(Sn/8, Bn), 256, BALL_SMEM>>>(xyz);
    build_pt<<<(Bn*Nn)/256, 256>>>(xyz, pts);

    // layer 1: gather-conv, pre-act -> g_A1, stats
    conv1_kernel<<<Pn/256, 256>>>(W0, b0);
    reduce_stats_kernel<<<64, 256>>>(Pn/256, 64, 0, g0, be0);

    // layer 2: conv (fused BN1+ReLU on load), pre-act -> g_A2, stats
    convN_kernel<64,1,false><<<Pn/256, 256>>>(pA1, W1, b1, pA2);
    reduce_stats_kernel<<<64, 256>>>(Pn/256, 64, 1, g1, be1);

    // layer 3: conv (fused BN2+ReLU on load) + k-max of pre-act -> g_M, stats
    convN_kernel<128,2,true><<<Pn/128, 256>>>(pA2, W2, b2, nullptr);
    reduce_stats_kernel<<<128, 256>>>(Pn/128, 128, 2, g2, be2);

    // BN3 + ReLU on pooled maxima -> output
    finalize_kernel<<<(128*Sg)/256, 256>>>(outpts);
}

// round 11
// speedup vs baseline: 1.8031x; 1.0658x over previous
#include <cuda_runtime.h>
#include <cstdint>

#define Bn 16
#define Nn 4096
#define Sn 1024
#define Kn 32
#define Pn (Bn*Sn*Kn)   // 524288 positions
#define Sg (Bn*Sn)      // 16384 centroids
#define R2 0.01f

// ---------------- scratch ----------------
__device__ float g_newxyz[Bn*Sn*3];
__device__ int   g_ball[Bn*Sn*Kn];
__device__ float g_PT[(size_t)Bn*Nn*68];
__device__ float g_A1[(size_t)64*Pn];
__device__ float g_A2[(size_t)64*Pn];
__device__ float g_M [(size_t)128*Sg];
__device__ float g_p1[(size_t)8192*128];
__device__ float g_p2[(size_t)8192*128];
__device__ float g_scale[3][128];
__device__ float g_shift[3][128];

// ---------------- f32x2 helpers ----------------
union F2 { unsigned long long u; float2 f; };

__device__ __forceinline__ unsigned long long fma2(unsigned long long a,
                                                   unsigned long long b,
                                                   unsigned long long c)
{
    unsigned long long d;
    asm("fma.rn.f32x2 %0, %1, %2, %3;" : "=l"(d) : "l"(a), "l"(b), "l"(c));
    return d;
}
__device__ __forceinline__ unsigned long long pack2(float x, float y)
{
    unsigned long long r;
    asm("mov.b64 %0, {%1, %2};" : "=l"(r) : "r"(__float_as_uint(x)), "r"(__float_as_uint(y)));
    return r;
}
__device__ __forceinline__ unsigned long long splat2(float x)
{
    unsigned long long r;
    asm("mov.b64 %0, {%1, %1};" : "=l"(r) : "r"(__float_as_uint(x)));
    return r;
}

// ---------------- FPS ----------------
// 256 threads x 16 points in registers. One barrier per iteration:
// REDUX warp argmax + double-buffered cross-warp partials reduced
// redundantly by every warp.  (validated correct in R10: output0 exact)
__global__ __launch_bounds__(256) void fps_kernel(const float* __restrict__ xyz,
                                                  float* __restrict__ out)
{
    extern __shared__ float sm[];
    float* sx = sm;
    float* sy = sm + Nn;
    float* sz = sm + 2*Nn;
    int*      sidx = (int*)(sm + 3*Nn);                 // 1024
    unsigned* rv   = (unsigned*)(sm + 3*Nn + Sn);       // [2][8]
    unsigned* ri   = rv + 16;                           // [2][8]

    int b = blockIdx.x, t = threadIdx.x;
    int lane = t & 31, w = t >> 5;
    const float* xb = xyz + (size_t)b*3*Nn;
    for (int i = t; i < Nn; i += 256) {
        sx[i] = xb[i]; sy[i] = xb[Nn+i]; sz[i] = xb[2*Nn+i];
    }
    __syncthreads();

    float px[16], py[16], pz[16], dm[16];
#pragma unroll
    for (int j = 0; j < 16; j++) {
        int n = t + j*256;
        px[j]=sx[n]; py[j]=sy[n]; pz[j]=sz[n]; dm[j]=1e10f;
    }
    if (t == 0) sidx[0] = 0;
    int fcur = 0;

    for (int it = 1; it < Sn; it++) {
        float cx = sx[fcur], cy = sy[fcur], cz = sz[fcur];
        float bv = -1.f; int bi = 0;
#pragma unroll
        for (int j = 0; j < 16; j++) {
            float dx = __fadd_rn(px[j], -cx);
            float dy = __fadd_rn(py[j], -cy);
            float dz = __fadd_rn(pz[j], -cz);
            float d  = __fadd_rn(__fadd_rn(__fmul_rn(dx,dx), __fmul_rn(dy,dy)), __fmul_rn(dz,dz));
            float nd = fminf(dm[j], d);
            dm[j] = nd;
            if (nd > bv) { bv = nd; bi = t + j*256; }   // j asc => lowest n kept on tie
        }
        unsigned vb   = __float_as_uint(bv);
        unsigned wmax = __reduce_max_sync(0xffffffffu, vb);
        unsigned cand = (vb == wmax) ? (unsigned)bi : 0xffffffffu;
        unsigned widx = __reduce_min_sync(0xffffffffu, cand);
        int pb = (it & 1) * 8;
        if (lane == 0) { rv[pb + w] = wmax; ri[pb + w] = widx; }
        __syncthreads();
        unsigned pv = (lane < 8) ? rv[pb + lane] : 0u;
        unsigned pi = (lane < 8) ? ri[pb + lane] : 0xffffffffu;
        unsigned gmax = __reduce_max_sync(0xffffffffu, pv);
        unsigned c2 = (lane < 8 && pv == gmax) ? pi : 0xffffffffu;
        fcur = (int)__reduce_min_sync(0xffffffffu, c2);
        if (t == 0) sidx[it] = fcur;
    }
    __syncthreads();

    for (int s = t; s < Sn; s += 256) {
        int n = sidx[s];
        float x = sx[n], y = sy[n], z = sz[n];
        g_newxyz[(b*Sn+s)*3+0] = x;
        g_newxyz[(b*Sn+s)*3+1] = y;
        g_newxyz[(b*Sn+s)*3+2] = z;
        out[((size_t)b*3+0)*Sn + s] = x;
        out[((size_t)b*3+1)*Sn + s] = y;
        out[((size_t)b*3+2)*Sn + s] = z;
    }
}

// ---------------- ball query ----------------
__global__ void ball_kernel(const float* __restrict__ xyz)
{
    extern __shared__ float bsm[];
    float* sx = bsm;
    float* sy = bsm + Nn;
    float* sz = bsm + 2*Nn;
    float* sn = bsm + 3*Nn;

    int b = blockIdx.y, t = threadIdx.x;
    const float* xb = xyz + (size_t)b*3*Nn;
    for (int i = t; i < Nn; i += 256) {
        float x = xb[i], y = xb[Nn+i], z = xb[2*Nn+i];
        sx[i]=x; sy[i]=y; sz[i]=z;
        sn[i] = __fadd_rn(__fadd_rn(__fmul_rn(x,x), __fmul_rn(y,y)), __fmul_rn(z,z));
    }
    __syncthreads();

    int w = t >> 5, lane = t & 31;
    int s = blockIdx.x*8 + w;
    const float* ctr = &g_newxyz[(b*Sn+s)*3];
    float cx = ctr[0], cy = ctr[1], cz = ctr[2];
    float cn = __fadd_rn(__fadd_rn(__fmul_rn(cx,cx), __fmul_rn(cy,cy)), __fmul_rn(cz,cz));

    int* dst = &g_ball[((size_t)b*Sn+s)*Kn];
    int cnt = 0, first = -1;
    for (int j = 0; j < Nn/32; j++) {
        int n = j*32 + lane;
        float dot = __fadd_rn(__fadd_rn(__fmul_rn(sx[n],cx), __fmul_rn(sy[n],cy)), __fmul_rn(sz[n],cz));
        float d = __fadd_rn(__fadd_rn(__fmul_rn(-2.f,dot), cn), sn[n]);
        bool in = !(d > R2);
        unsigned m = __ballot_sync(0xffffffffu, in);
        if (m) {
            if (first < 0) first = j*32 + __ffs(m) - 1;
            if (in) {
                int pos = cnt + __popc(m & ((1u<<lane)-1u));
                if (pos < Kn) dst[pos] = n;
            }
            cnt += __popc(m);
            if (cnt >= Kn) break;
        }
    }
    for (int pos = cnt + lane; pos < Kn; pos += 32) dst[pos] = first;
}

// ---------------- point table transpose ----------------
__global__ void build_pt(const float* __restrict__ xyz, const float* __restrict__ pts)
{
    int i = blockIdx.x*256 + threadIdx.x;
    int b = i >> 12, n = i & 4095;
    float* dst = &g_PT[(size_t)i*68];
    dst[0] = xyz[((size_t)b*3+0)*Nn + n];
    dst[1] = xyz[((size_t)b*3+1)*Nn + n];
    dst[2] = xyz[((size_t)b*3+2)*Nn + n];
#pragma unroll 4
    for (int c = 0; c < 64; c++) dst[3+c] = pts[((size_t)b*64+c)*Nn + n];
    dst[67] = 0.f;
}

// ---------------- per-subgroup stats output ----------------
// Each PL-thread subgroup owns channels [co0, co0+8) and covers ALL positions
// of the block for them, so the subgroup partial IS the block partial:
// reduce over PL lanes (offsets PL/2..1; lanes >= PL of intermediate sums are
// never read, so the half-warp tree at lanes 0/16 is exact) and write straight
// to global. No smem, no barrier.
template<int PL, int COUT>
__device__ __forceinline__ void stats_out(float (&s1)[8], float (&s2)[8],
                                          int co0, int nbIdx)
{
    int t = threadIdx.x;
#pragma unroll
    for (int j = 0; j < 8; j++) {
        float a = s1[j], bb = s2[j];
#pragma unroll
        for (int o = PL/2; o; o >>= 1) {
            a  += __shfl_down_sync(0xffffffffu, a,  o);
            bb += __shfl_down_sync(0xffffffffu, bb, o);
        }
        if ((t % PL) == 0) {
            g_p1[(size_t)nbIdx*COUT + co0 + j] = a;
            g_p2[(size_t)nbIdx*COUT + co0 + j] = bb;
        }
    }
}

// 8-channel x (2 position-pair) FFMA2 block
__device__ __forceinline__ void ffma2_8(F2 (&acc)[16],
                                        unsigned long long x01, unsigned long long x23,
                                        const float* wa, const float* wb)
{
#pragma unroll
    for (int j = 0; j < 4; j++) {
        unsigned long long s = splat2(wa[j]);
        acc[j*2  ].u = fma2(x01, s, acc[j*2  ].u);
        acc[j*2+1].u = fma2(x23, s, acc[j*2+1].u);
    }
#pragma unroll
    for (int j = 0; j < 4; j++) {
        unsigned long long s = splat2(wb[j]);
        acc[8+j*2  ].u = fma2(x01, s, acc[8+j*2  ].u);
        acc[8+j*2+1].u = fma2(x23, s, acc[8+j*2+1].u);
    }
}

// ---------------- layer 1: gather + conv 67->64 (FFMA2) ----------------
// 256 thr: 8 groups x 8 channels, 32 thr x 4 positions => 128 pos/block.
__global__ __launch_bounds__(256, 2) void conv1_kernel(const float* __restrict__ W0,
                                                       const float* __restrict__ b0)
{
    __shared__ float Wt[68*64];          // c-major: Wt[c*64+j]
    int t = threadIdx.x;
    for (int i = t; i < 68*64; i += 256) {
        int c = i >> 6, j = i & 63;
        Wt[i] = (c < 67) ? W0[j*67 + c] : 0.f;
    }
    __syncthreads();

    int grp = t >> 5, pl = t & 31, co0 = grp*8;
    int p0 = blockIdx.x*128 + pl*4;
    int b  = p0 >> 15;
    int sg = p0 >> 5;
    float cx = g_newxyz[sg*3], cy = g_newxyz[sg*3+1], cz = g_newxyz[sg*3+2];

    int4 bnix = *(const int4*)&g_ball[p0];
    const float4* r0 = (const float4*)&g_PT[((size_t)(b<<12) + bnix.x)*68];
    const float4* r1 = (const float4*)&g_PT[((size_t)(b<<12) + bnix.y)*68];
    const float4* r2 = (const float4*)&g_PT[((size_t)(b<<12) + bnix.z)*68];
    const float4* r3 = (const float4*)&g_PT[((size_t)(b<<12) + bnix.w)*68];

    F2 acc[16];   // [j][pair]: j=0..7 channels, pair0=(q0,q1) pair1=(q2,q3)
#pragma unroll
    for (int j = 0; j < 8; j++) {
        int jg = co0 + j;
        float base = b0[jg] - (Wt[jg]*cx + Wt[64+jg]*cy + Wt[128+jg]*cz);
        acc[j*2  ].f = make_float2(base, base);
        acc[j*2+1].f = make_float2(base, base);
    }

#pragma unroll 4
    for (int cc = 0; cc < 17; cc++) {
        float4 v0 = r0[cc], v1 = r1[cc], v2 = r2[cc], v3 = r3[cc];
        const float* a0 = (const float*)&v0;
        const float* a1 = (const float*)&v1;
        const float* a2 = (const float*)&v2;
        const float* a3 = (const float*)&v3;
#pragma unroll
        for (int c4 = 0; c4 < 4; c4++) {
            int c = cc*4 + c4;
            unsigned long long x01 = pack2(a0[c4], a1[c4]);
            unsigned long long x23 = pack2(a2[c4], a3[c4]);
            const float4* wp = (const float4*)&Wt[c*64 + co0];
            float4 wA = wp[0], wB = wp[1];
            ffma2_8(acc, x01, x23, (const float*)&wA, (const float*)&wB);
        }
    }

    float s1[8], s2[8];
#pragma unroll
    for (int j = 0; j < 8; j++) {
        float a0 = acc[j*2].f.x, a1 = acc[j*2].f.y;
        float a2 = acc[j*2+1].f.x, a3 = acc[j*2+1].f.y;
        *(float4*)&g_A1[(size_t)(co0+j)*Pn + p0] = make_float4(a0,a1,a2,a3);
        s1[j] = a0+a1+a2+a3;
        s2[j] = a0*a0+a1*a1+a2*a2+a3*a3;
    }
    stats_out<32,64>(s1, s2, co0, blockIdx.x);
}

// ---------------- layers 2/3 (FFMA2, fused input BN+ReLU) ----------------
template<int COUT, int LAYER, bool POOL>
__global__ __launch_bounds__(256, 2) void convN_kernel(const float* __restrict__ A,
                                                       const float* __restrict__ Wg,
                                                       const float* __restrict__ bg,
                                                       float* __restrict__ Aout)
{
    constexpr int CIN = 64;
    constexpr int G   = COUT / 8;          // 8 or 16
    constexpr int PL  = 256 / G;           // 32 or 16
    constexpr int PPB = PL * 4;            // 128 or 64

    __shared__ float Wt[CIN*COUT];         // c-major
    __shared__ float sc[CIN], sh[CIN];

    int t = threadIdx.x;
    for (int i = t; i < CIN*COUT; i += 256) {
        int c = i / COUT, j = i % COUT;
        Wt[i] = Wg[j*CIN + c];
    }
    if (t < CIN) { sc[t] = g_scale[LAYER-1][t]; sh[t] = g_shift[LAYER-1][t]; }
    __syncthreads();

    int grp = t / PL, pl = t % PL, co0 = grp*8;
    int p0 = blockIdx.x*PPB + pl*4;

    F2 acc[16];
#pragma unroll
    for (int j = 0; j < 8; j++) {
        float base = bg[co0+j];
        acc[j*2  ].f = make_float2(base, base);
        acc[j*2+1].f = make_float2(base, base);
    }

#pragma unroll 4
    for (int c = 0; c < CIN; c++) {
        float4 v = *(const float4*)&A[(size_t)c*Pn + p0];
        float s = sc[c], h = sh[c];
        float x0 = fmaxf(fmaf(v.x, s, h), 0.f);
        float x1 = fmaxf(fmaf(v.y, s, h), 0.f);
        float x2 = fmaxf(fmaf(v.z, s, h), 0.f);
        float x3 = fmaxf(fmaf(v.w, s, h), 0.f);
        unsigned long long x01 = pack2(x0, x1);
        unsigned long long x23 = pack2(x2, x3);
        const float4* wp = (const float4*)&Wt[c*COUT + co0];
        float4 wA = wp[0], wB = wp[1];
        ffma2_8(acc, x01, x23, (const float*)&wA, (const float*)&wB);
    }

    float s1[8], s2[8];
#pragma unroll
    for (int j = 0; j < 8; j++) {
        float a0 = acc[j*2].f.x, a1 = acc[j*2].f.y;
        float a2 = acc[j*2+1].f.x, a3 = acc[j*2+1].f.y;
        s1[j] = a0+a1+a2+a3;
        s2[j] = a0*a0+a1*a1+a2*a2+a3*a3;
        if (!POOL)
            *(float4*)&Aout[(size_t)(co0+j)*Pn + p0] = make_float4(a0,a1,a2,a3);
    }
    if (POOL) {
        // k-max over pre-act (scale>0 => commutes with BN+ReLU).
        // 8 consecutive lanes (same pl>>3 subgroup) share one centroid.
        int sgG = p0 >> 5;
#pragma unroll
        for (int j = 0; j < 8; j++) {
            float m = fmaxf(fmaxf(acc[j*2].f.x, acc[j*2].f.y),
                            fmaxf(acc[j*2+1].f.x, acc[j*2+1].f.y));
            m = fmaxf(m, __shfl_xor_sync(0xffffffffu, m, 1));
            m = fmaxf(m, __shfl_xor_sync(0xffffffffu, m, 2));
            m = fmaxf(m, __shfl_xor_sync(0xffffffffu, m, 4));
            if ((pl & 7) == j)
                g_M[(size_t)(co0+j)*Sg + sgG] = m;
        }
    }
    stats_out<PL,COUT>(s1, s2, co0, blockIdx.x);
}

// ---------------- stats -> scale/shift ----------------
__global__ void reduce_stats_kernel(int NB, int COUT, int layer,
                                    const float* __restrict__ gamma,
                                    const float* __restrict__ beta)
{
    int co = blockIdx.x, t = threadIdx.x;
    double s1 = 0.0, s2 = 0.0;
    for (int i = t; i < NB; i += 256) {
        s1 += (double)g_p1[(size_t)i*COUT + co];
        s2 += (double)g_p2[(size_t)i*COUT + co];
    }
    __shared__ double r1[256], r2[256];
    r1[t] = s1; r2[t] = s2;
    __syncthreads();
    for (int o = 128; o; o >>= 1) {
        if (t < o) { r1[t] += r1[t+o]; r2[t] += r2[t+o]; }
        __syncthreads();
    }
    if (t == 0) {
        double mu  = r1[0] * (1.0 / Pn);
        double var = r2[0] * (1.0 / Pn) - mu*mu;
        double scd = (double)gamma[co] / sqrt(var + 1e-5);
        g_scale[layer][co] = (float)scd;
        g_shift[layer][co] = (float)((double)beta[co] - mu*scd);
    }
}

// ---------------- finalize: BN3+ReLU on pooled pre-act max ----------------
__global__ void finalize_kernel(float* __restrict__ outpts)
{
    int i = blockIdx.x*256 + threadIdx.x;
    int co = i >> 14, sg = i & 16383;
    float y = fmaf(g_M[i], g_scale[2][co], g_shift[2][co]);
    y = fmaxf(y, 0.f);
    int b = sg >> 10, s = sg & 1023;
    outpts[((size_t)(b*128 + co))*1024 + s] = y;
}

// ---------------- launch ----------------
extern "C" void kernel_launch(void* const* d_in, const int* in_sizes, int n_in,
                              void* d_out, int out_size)
{
    const float* xyz = (const float*)d_in[0];
    const float* pts = (const float*)d_in[1];
    const float* W0  = (const float*)d_in[2];
    const float* b0  = (const float*)d_in[3];
    const float* g0  = (const float*)d_in[4];
    const float* be0 = (const float*)d_in[5];
    const float* W1  = (const float*)d_in[6];
    const float* b1  = (const float*)d_in[7];
    const float* g1  = (const float*)d_in[8];
    const float* be1 = (const float*)d_in[9];
    const float* W2  = (const float*)d_in[10];
    const float* b2  = (const float*)d_in[11];
    const float* g2  = (const float*)d_in[12];
    const float* be2 = (const float*)d_in[13];

    float* out    = (float*)d_out;
    float* outpts = out + (size_t)Bn*3*Sn;

    const int FPS_SMEM  = (3*Nn + Sn + 32) * 4 + 256;  // ~53.5 KB
    const int BALL_SMEM = 4*Nn*4;                      // 64 KB
    cudaFuncSetAttribute(fps_kernel,  cudaFuncAttributeMaxDynamicSharedMemorySize, FPS_SMEM);
    cudaFuncSetAttribute(ball_kernel, cudaFuncAttributeMaxDynamicSharedMemorySize, BALL_SMEM);

    float *pA1 = nullptr, *pA2 = nullptr;
    cudaGetSymbolAddress((void**)&pA1, g_A1);
    cudaGetSymbolAddress((void**)&pA2, g_A2);

    fps_kernel<<<Bn, 256, FPS_SMEM>>>(xyz, out);
    ball_kernel<<<dim3(Sn/8, Bn), 256, BALL_SMEM>>>(xyz);
    build_pt<<<(Bn*Nn)/256, 256>>>(xyz, pts);

    // layer 1: gather-conv, pre-act -> g_A1, stats
    conv1_kernel<<<Pn/128, 256>>>(W0, b0);
    reduce_stats_kernel<<<64, 256>>>(Pn/128, 64, 0, g0, be0);

    // layer 2: conv (fused BN1+ReLU on load), pre-act -> g_A2, stats
    convN_kernel<64,1,false><<<Pn/128, 256>>>(pA1, W1, b1, pA2);
    reduce_stats_kernel<<<64, 256>>>(Pn/128, 64, 1, g1, be1);

    // layer 3: conv (fused BN2+ReLU on load) + k-max of pre-act -> g_M, stats
    convN_kernel<128,2,true><<<Pn/64, 256>>>(pA2, W2, b2, nullptr);
    reduce_stats_kernel<<<128, 256>>>(Pn/64, 128, 2, g2, be2);

    // BN3 + ReLU on pooled maxima -> output
    finalize_kernel<<<(128*Sg)/256, 256>>>(outpts);
}

// round 12
// speedup vs baseline: 2.1796x; 1.2088x over previous
#include <cuda_runtime.h>
#include <cstdint>

#define Bn 16
#define Nn 4096
#define Sn 1024
#define Kn 32
#define Pn (Bn*Sn*Kn)   // 524288 positions
#define Sg (Bn*Sn)      // 16384 centroids
#define R2 0.01f

// ---------------- scratch ----------------
__device__ float g_newxyz[Bn*Sn*3];
__device__ int   g_ball[Bn*Sn*Kn];
__device__ float g_PT[(size_t)Bn*Nn*68];
__device__ float g_A1[(size_t)64*Pn];
__device__ float g_A2[(size_t)64*Pn];
__device__ float g_M [(size_t)128*Sg];
__device__ float g_p1[(size_t)8192*128];
__device__ float g_p2[(size_t)8192*128];
__device__ float g_scale[3][128];
__device__ float g_shift[3][128];

// ---------------- f32x2 helpers ----------------
union F2 { unsigned long long u; float2 f; };
typedef unsigned long long u64;

__device__ __forceinline__ u64 fma2(u64 a, u64 b, u64 c)
{
    u64 d;
    asm("fma.rn.f32x2 %0, %1, %2, %3;" : "=l"(d) : "l"(a), "l"(b), "l"(c));
    return d;
}
__device__ __forceinline__ u64 pack2(float x, float y)
{
    u64 r;
    asm("mov.b64 %0, {%1, %2};" : "=l"(r) : "r"(__float_as_uint(x)), "r"(__float_as_uint(y)));
    return r;
}
__device__ __forceinline__ u64 splat2(float x)
{
    u64 r;
    asm("mov.b64 %0, {%1, %1};" : "=l"(r) : "r"(__float_as_uint(x)));
    return r;
}

// ---------------- FPS (validated) ----------------
__global__ __launch_bounds__(256) void fps_kernel(const float* __restrict__ xyz,
                                                  float* __restrict__ out)
{
    extern __shared__ float sm[];
    float* sx = sm;
    float* sy = sm + Nn;
    float* sz = sm + 2*Nn;
    int*      sidx = (int*)(sm + 3*Nn);
    unsigned* rv   = (unsigned*)(sm + 3*Nn + Sn);
    unsigned* ri   = rv + 16;

    int b = blockIdx.x, t = threadIdx.x;
    int lane = t & 31, w = t >> 5;
    const float* xb = xyz + (size_t)b*3*Nn;
    for (int i = t; i < Nn; i += 256) {
        sx[i] = xb[i]; sy[i] = xb[Nn+i]; sz[i] = xb[2*Nn+i];
    }
    __syncthreads();

    float px[16], py[16], pz[16], dm[16];
#pragma unroll
    for (int j = 0; j < 16; j++) {
        int n = t + j*256;
        px[j]=sx[n]; py[j]=sy[n]; pz[j]=sz[n]; dm[j]=1e10f;
    }
    if (t == 0) sidx[0] = 0;
    int fcur = 0;

    for (int it = 1; it < Sn; it++) {
        float cx = sx[fcur], cy = sy[fcur], cz = sz[fcur];
        float bv = -1.f; int bi = 0;
#pragma unroll
        for (int j = 0; j < 16; j++) {
            float dx = __fadd_rn(px[j], -cx);
            float dy = __fadd_rn(py[j], -cy);
            float dz = __fadd_rn(pz[j], -cz);
            float d  = __fadd_rn(__fadd_rn(__fmul_rn(dx,dx), __fmul_rn(dy,dy)), __fmul_rn(dz,dz));
            float nd = fminf(dm[j], d);
            dm[j] = nd;
            if (nd > bv) { bv = nd; bi = t + j*256; }
        }
        unsigned vb   = __float_as_uint(bv);
        unsigned wmax = __reduce_max_sync(0xffffffffu, vb);
        unsigned cand = (vb == wmax) ? (unsigned)bi : 0xffffffffu;
        unsigned widx = __reduce_min_sync(0xffffffffu, cand);
        int pb = (it & 1) * 8;
        if (lane == 0) { rv[pb + w] = wmax; ri[pb + w] = widx; }
        __syncthreads();
        unsigned pv = (lane < 8) ? rv[pb + lane] : 0u;
        unsigned pi = (lane < 8) ? ri[pb + lane] : 0xffffffffu;
        unsigned gmax = __reduce_max_sync(0xffffffffu, pv);
        unsigned c2 = (lane < 8 && pv == gmax) ? pi : 0xffffffffu;
        fcur = (int)__reduce_min_sync(0xffffffffu, c2);
        if (t == 0) sidx[it] = fcur;
    }
    __syncthreads();

    for (int s = t; s < Sn; s += 256) {
        int n = sidx[s];
        float x = sx[n], y = sy[n], z = sz[n];
        g_newxyz[(b*Sn+s)*3+0] = x;
        g_newxyz[(b*Sn+s)*3+1] = y;
        g_newxyz[(b*Sn+s)*3+2] = z;
        out[((size_t)b*3+0)*Sn + s] = x;
        out[((size_t)b*3+1)*Sn + s] = y;
        out[((size_t)b*3+2)*Sn + s] = z;
    }
}

// ---------------- ball query ----------------
__global__ void ball_kernel(const float* __restrict__ xyz)
{
    extern __shared__ float bsm[];
    float* sx = bsm;
    float* sy = bsm + Nn;
    float* sz = bsm + 2*Nn;
    float* sn = bsm + 3*Nn;

    int b = blockIdx.y, t = threadIdx.x;
    const float* xb = xyz + (size_t)b*3*Nn;
    for (int i = t; i < Nn; i += 256) {
        float x = xb[i], y = xb[Nn+i], z = xb[2*Nn+i];
        sx[i]=x; sy[i]=y; sz[i]=z;
        sn[i] = __fadd_rn(__fadd_rn(__fmul_rn(x,x), __fmul_rn(y,y)), __fmul_rn(z,z));
    }
    __syncthreads();

    int w = t >> 5, lane = t & 31;
    int s = blockIdx.x*8 + w;
    const float* ctr = &g_newxyz[(b*Sn+s)*3];
    float cx = ctr[0], cy = ctr[1], cz = ctr[2];
    float cn = __fadd_rn(__fadd_rn(__fmul_rn(cx,cx), __fmul_rn(cy,cy)), __fmul_rn(cz,cz));

    int* dst = &g_ball[((size_t)b*Sn+s)*Kn];
    int cnt = 0, first = -1;
    for (int j = 0; j < Nn/32; j++) {
        int n = j*32 + lane;
        float dot = __fadd_rn(__fadd_rn(__fmul_rn(sx[n],cx), __fmul_rn(sy[n],cy)), __fmul_rn(sz[n],cz));
        float d = __fadd_rn(__fadd_rn(__fmul_rn(-2.f,dot), cn), sn[n]);
        bool in = !(d > R2);
        unsigned m = __ballot_sync(0xffffffffu, in);
        if (m) {
            if (first < 0) first = j*32 + __ffs(m) - 1;
            if (in) {
                int pos = cnt + __popc(m & ((1u<<lane)-1u));
                if (pos < Kn) dst[pos] = n;
            }
            cnt += __popc(m);
            if (cnt >= Kn) break;
        }
    }
    for (int pos = cnt + lane; pos < Kn; pos += 32) dst[pos] = first;
}

// ---------------- point table transpose ----------------
__global__ void build_pt(const float* __restrict__ xyz, const float* __restrict__ pts)
{
    int i = blockIdx.x*256 + threadIdx.x;
    int b = i >> 12, n = i & 4095;
    float* dst = &g_PT[(size_t)i*68];
    dst[0] = xyz[((size_t)b*3+0)*Nn + n];
    dst[1] = xyz[((size_t)b*3+1)*Nn + n];
    dst[2] = xyz[((size_t)b*3+2)*Nn + n];
#pragma unroll 4
    for (int c = 0; c < 64; c++) dst[3+c] = pts[((size_t)b*64+c)*Nn + n];
    dst[67] = 0.f;
}

// ---------------- per-subgroup stats output (no smem, no barrier) ----------------
template<int PL, int COUT>
__device__ __forceinline__ void stats_out(float (&s1)[8], float (&s2)[8],
                                          int co0, int nbIdx)
{
    int t = threadIdx.x;
#pragma unroll
    for (int j = 0; j < 8; j++) {
        float a = s1[j], bb = s2[j];
#pragma unroll
        for (int o = PL/2; o; o >>= 1) {
            a  += __shfl_down_sync(0xffffffffu, a,  o);
            bb += __shfl_down_sync(0xffffffffu, bb, o);
        }
        if ((t % PL) == 0) {
            g_p1[(size_t)nbIdx*COUT + co0 + j] = a;
            g_p2[(size_t)nbIdx*COUT + co0 + j] = bb;
        }
    }
}

// ---------------- layer 1: gather + conv 67->64 ----------------
// 256 thr: 8 groups x 8 channels, 32 lanes x 8 positions => 256 pos/block.
// Weights pre-splatted {w,w} in smem; activations packed cross-position (4 ALU
// packs per 32 fma2).
__global__ __launch_bounds__(256, 2) void conv1_kernel(const float* __restrict__ W0,
                                                       const float* __restrict__ b0)
{
    __shared__ u64 Wd[68*64];            // c-major, splatted: Wd[c*64+j] = {w,w}
    int t = threadIdx.x;
    for (int i = t; i < 68*64; i += 256) {
        int c = i >> 6, j = i & 63;
        float w = (c < 67) ? W0[j*67 + c] : 0.f;
        Wd[i] = splat2(w);
    }
    __syncthreads();

    int grp = t >> 5, pl = t & 31, co0 = grp*8;
    int p0 = blockIdx.x*256 + pl*8;
    int b  = p0 >> 15;
    int sg = p0 >> 5;                    // all 8 positions share one centroid
    float cx = g_newxyz[sg*3], cy = g_newxyz[sg*3+1], cz = g_newxyz[sg*3+2];

    int4 i0 = *(const int4*)&g_ball[p0];
    int4 i1 = *(const int4*)&g_ball[p0+4];
    const float4* r[8];
    r[0] = (const float4*)&g_PT[((size_t)(b<<12) + i0.x)*68];
    r[1] = (const float4*)&g_PT[((size_t)(b<<12) + i0.y)*68];
    r[2] = (const float4*)&g_PT[((size_t)(b<<12) + i0.z)*68];
    r[3] = (const float4*)&g_PT[((size_t)(b<<12) + i0.w)*68];
    r[4] = (const float4*)&g_PT[((size_t)(b<<12) + i1.x)*68];
    r[5] = (const float4*)&g_PT[((size_t)(b<<12) + i1.y)*68];
    r[6] = (const float4*)&g_PT[((size_t)(b<<12) + i1.z)*68];
    r[7] = (const float4*)&g_PT[((size_t)(b<<12) + i1.w)*68];

    F2 acc[32];                          // [j][pair p]: j*4+p
#pragma unroll
    for (int j = 0; j < 8; j++) {
        int jg = co0 + j;
        float w0x = W0[jg*67+0], w0y = W0[jg*67+1], w0z = W0[jg*67+2];
        float base = b0[jg] - (w0x*cx + w0y*cy + w0z*cz);
        u64 b2v = pack2(base, base);
#pragma unroll
        for (int p = 0; p < 4; p++) acc[j*4+p].u = b2v;
    }

#pragma unroll 1
    for (int cc = 0; cc < 17; cc++) {
        float4 v0 = r[0][cc], v1 = r[1][cc], v2 = r[2][cc], v3 = r[3][cc];
        float4 v4 = r[4][cc], v5 = r[5][cc], v6 = r[6][cc], v7 = r[7][cc];
        const float* a0 = (const float*)&v0; const float* a1 = (const float*)&v1;
        const float* a2 = (const float*)&v2; const float* a3 = (const float*)&v3;
        const float* a4 = (const float*)&v4; const float* a5 = (const float*)&v5;
        const float* a6 = (const float*)&v6; const float* a7 = (const float*)&v7;
#pragma unroll
        for (int c4 = 0; c4 < 4; c4++) {
            int c = cc*4 + c4;
            u64 x[4];
            x[0] = pack2(a0[c4], a1[c4]);
            x[1] = pack2(a2[c4], a3[c4]);
            x[2] = pack2(a4[c4], a5[c4]);
            x[3] = pack2(a6[c4], a7[c4]);
            const ulonglong2* wp = (const ulonglong2*)&Wd[c*64 + co0];
            ulonglong2 wq0 = wp[0], wq1 = wp[1], wq2 = wp[2], wq3 = wp[3];
            u64 wv[8] = {wq0.x, wq0.y, wq1.x, wq1.y, wq2.x, wq2.y, wq3.x, wq3.y};
#pragma unroll
            for (int j = 0; j < 8; j++)
#pragma unroll
                for (int p = 0; p < 4; p++)
                    acc[j*4+p].u = fma2(x[p], wv[j], acc[j*4+p].u);
        }
    }

    float s1[8], s2[8];
#pragma unroll
    for (int j = 0; j < 8; j++) {
        float a0 = acc[j*4+0].f.x, a1 = acc[j*4+0].f.y;
        float a2 = acc[j*4+1].f.x, a3 = acc[j*4+1].f.y;
        float a4 = acc[j*4+2].f.x, a5 = acc[j*4+2].f.y;
        float a6 = acc[j*4+3].f.x, a7 = acc[j*4+3].f.y;
        float* dst = &g_A1[(size_t)(co0+j)*Pn + p0];
        *(float4*)dst       = make_float4(a0,a1,a2,a3);
        *(float4*)(dst + 4) = make_float4(a4,a5,a6,a7);
        s1[j] = (a0+a1+a2+a3) + (a4+a5+a6+a7);
        s2[j] = (a0*a0+a1*a1+a2*a2+a3*a3) + (a4*a4+a5*a5+a6*a6+a7*a7);
    }
    stats_out<32,64>(s1, s2, co0, blockIdx.x);
}

// ---------------- layers 2/3: smem-staged conv (pure fma2 inner) ----------------
// Stage: apply BN+ReLU ONCE per element into a [c][pos] smem tile.
// Inner: activations read as u64 pairs from smem, weights pre-splatted {w,w}.
template<int COUT, int LAYER, bool POOL>
__global__ __launch_bounds__(256, 2) void convN_kernel(const float* __restrict__ A,
                                                       const float* __restrict__ Wg,
                                                       const float* __restrict__ bg,
                                                       float* __restrict__ Aout)
{
    constexpr int CIN = 64;
    constexpr int G   = COUT / 8;          // 8 or 16
    constexpr int PL  = 256 / G;           // 32 or 16
    constexpr int PPB = PL * 8;            // 256 or 128

    extern __shared__ char dyn[];
    u64*   Wd   = (u64*)dyn;                            // CIN*COUT splatted
    float* tile = (float*)(dyn + (size_t)CIN*COUT*8);   // [c][PPB]
    __shared__ float sc[CIN], sh[CIN];

    int t = threadIdx.x;
    if (t < CIN) { sc[t] = g_scale[LAYER-1][t]; sh[t] = g_shift[LAYER-1][t]; }
    for (int i = t; i < CIN*COUT; i += 256) {
        int c = i / COUT, j = i % COUT;
        Wd[i] = splat2(Wg[j*CIN + c]);
    }
    __syncthreads();

    // stage activations with BN+ReLU applied once
    size_t base = (size_t)blockIdx.x * PPB;
    constexpr int F4R = PPB/4;                 // float4s per channel row
#pragma unroll 4
    for (int k = t; k < CIN*F4R; k += 256) {
        int c = k / F4R, off = (k % F4R)*4;
        float4 v = *(const float4*)&A[(size_t)c*Pn + base + off];
        float s = sc[c], h = sh[c];
        v.x = fmaxf(fmaf(v.x, s, h), 0.f);
        v.y = fmaxf(fmaf(v.y, s, h), 0.f);
        v.z = fmaxf(fmaf(v.z, s, h), 0.f);
        v.w = fmaxf(fmaf(v.w, s, h), 0.f);
        *(float4*)&tile[c*PPB + off] = v;
    }
    __syncthreads();

    int grp = t / PL, pl = t % PL, co0 = grp*8;
    int p0 = blockIdx.x*PPB + pl*8;

    F2 acc[32];
#pragma unroll
    for (int j = 0; j < 8; j++) {
        u64 b2v = pack2(bg[co0+j], bg[co0+j]);
#pragma unroll
        for (int p = 0; p < 4; p++) acc[j*4+p].u = b2v;
    }

#pragma unroll 4
    for (int c = 0; c < CIN; c++) {
        const ulonglong2* xp = (const ulonglong2*)&tile[c*PPB + pl*8];
        ulonglong2 q0 = xp[0], q1 = xp[1];
        u64 x[4] = {q0.x, q0.y, q1.x, q1.y};
        const ulonglong2* wp = (const ulonglong2*)&Wd[c*COUT + co0];
        ulonglong2 wq0 = wp[0], wq1 = wp[1], wq2 = wp[2], wq3 = wp[3];
        u64 wv[8] = {wq0.x, wq0.y, wq1.x, wq1.y, wq2.x, wq2.y, wq3.x, wq3.y};
#pragma unroll
        for (int j = 0; j < 8; j++)
#pragma unroll
            for (int p = 0; p < 4; p++)
                acc[j*4+p].u = fma2(x[p], wv[j], acc[j*4+p].u);
    }

    float s1[8], s2[8];
#pragma unroll
    for (int j = 0; j < 8; j++) {
        float a0 = acc[j*4+0].f.x, a1 = acc[j*4+0].f.y;
        float a2 = acc[j*4+1].f.x, a3 = acc[j*4+1].f.y;
        float a4 = acc[j*4+2].f.x, a5 = acc[j*4+2].f.y;
        float a6 = acc[j*4+3].f.x, a7 = acc[j*4+3].f.y;
        s1[j] = (a0+a1+a2+a3) + (a4+a5+a6+a7);
        s2[j] = (a0*a0+a1*a1+a2*a2+a3*a3) + (a4*a4+a5*a5+a6*a6+a7*a7);
        if (!POOL) {
            float* dst = &Aout[(size_t)(co0+j)*Pn + p0];
            *(float4*)dst       = make_float4(a0,a1,a2,a3);
            *(float4*)(dst + 4) = make_float4(a4,a5,a6,a7);
        }
    }
    if (POOL) {
        // 4 consecutive lanes share one centroid (4 lanes x 8 pos = 32 k).
        // scale>0 => max commutes with BN+ReLU (applied in finalize).
        int sgG = p0 >> 5;
#pragma unroll
        for (int j = 0; j < 8; j++) {
            float m = fmaxf(fmaxf(fmaxf(acc[j*4+0].f.x, acc[j*4+0].f.y),
                                  fmaxf(acc[j*4+1].f.x, acc[j*4+1].f.y)),
                            fmaxf(fmaxf(acc[j*4+2].f.x, acc[j*4+2].f.y),
                                  fmaxf(acc[j*4+3].f.x, acc[j*4+3].f.y)));
            m = fmaxf(m, __shfl_xor_sync(0xffffffffu, m, 1));
            m = fmaxf(m, __shfl_xor_sync(0xffffffffu, m, 2));
            if ((pl & 3) == (j & 3))
                g_M[(size_t)(co0+j)*Sg + sgG] = m;
        }
    }
    stats_out<PL,COUT>(s1, s2, co0, blockIdx.x);
}

// ---------------- stats -> scale/shift ----------------
__global__ void reduce_stats_kernel(int NB, int COUT, int layer,
                                    const float* __restrict__ gamma,
                                    const float* __restrict__ beta)
{
    int co = blockIdx.x, t = threadIdx.x;
    double s1 = 0.0, s2 = 0.0;
    for (int i = t; i < NB; i += 256) {
        s1 += (double)g_p1[(size_t)i*COUT + co];
        s2 += (double)g_p2[(size_t)i*COUT + co];
    }
    __shared__ double r1[256], r2[256];
    r1[t] = s1; r2[t] = s2;
    __syncthreads();
    for (int o = 128; o; o >>= 1) {
        if (t < o) { r1[t] += r1[t+o]; r2[t] += r2[t+o]; }
        __syncthreads();
    }
    if (t == 0) {
        double mu  = r1[0] * (1.0 / Pn);
        double var = r2[0] * (1.0 / Pn) - mu*mu;
        double scd = (double)gamma[co] / sqrt(var + 1e-5);
        g_scale[layer][co] = (float)scd;
        g_shift[layer][co] = (float)((double)beta[co] - mu*scd);
    }
}

// ---------------- finalize: BN3+ReLU on pooled pre-act max ----------------
__global__ void finalize_kernel(float* __restrict__ outpts)
{
    int i = blockIdx.x*256 + threadIdx.x;
    int co = i >> 14, sg = i & 16383;
    float y = fmaf(g_M[i], g_scale[2][co], g_shift[2][co]);
    y = fmaxf(y, 0.f);
    int b = sg >> 10, s = sg & 1023;
    outpts[((size_t)(b*128 + co))*1024 + s] = y;
}

// ---------------- launch ----------------
extern "C" void kernel_launch(void* const* d_in, const int* in_sizes, int n_in,
                              void* d_out, int out_size)
{
    const float* xyz = (const float*)d_in[0];
    const float* pts = (const float*)d_in[1];
    const float* W0  = (const float*)d_in[2];
    const float* b0  = (const float*)d_in[3];
    const float* g0  = (const float*)d_in[4];
    const float* be0 = (const float*)d_in[5];
    const float* W1  = (const float*)d_in[6];
    const float* b1  = (const float*)d_in[7];
    const float* g1  = (const float*)d_in[8];
    const float* be1 = (const float*)d_in[9];
    const float* W2  = (const float*)d_in[10];
    const float* b2  = (const float*)d_in[11];
    const float* g2  = (const float*)d_in[12];
    const float* be2 = (const float*)d_in[13];

    float* out    = (float*)d_out;
    float* outpts = out + (size_t)Bn*3*Sn;

    const int FPS_SMEM  = (3*Nn + Sn + 32) * 4 + 256;
    const int BALL_SMEM = 4*Nn*4;
    // conv2: W 64*64*8=32KB + tile 64*256*4=64KB = 96KB
    // conv3: W 64*128*8=64KB + tile 64*128*4=32KB = 96KB
    const int CONV2_SMEM = 64*64*8 + 64*256*4;
    const int CONV3_SMEM = 64*128*8 + 64*128*4;
    cudaFuncSetAttribute(fps_kernel,  cudaFuncAttributeMaxDynamicSharedMemorySize, FPS_SMEM);
    cudaFuncSetAttribute(ball_kernel, cudaFuncAttributeMaxDynamicSharedMemorySize, BALL_SMEM);
    cudaFuncSetAttribute(convN_kernel<64,1,false>,
                         cudaFuncAttributeMaxDynamicSharedMemorySize, CONV2_SMEM);
    cudaFuncSetAttribute(convN_kernel<128,2,true>,
                         cudaFuncAttributeMaxDynamicSharedMemorySize, CONV3_SMEM);

    float *pA1 = nullptr, *pA2 = nullptr;
    cudaGetSymbolAddress((void**)&pA1, g_A1);
    cudaGetSymbolAddress((void**)&pA2, g_A2);

    fps_kernel<<<Bn, 256, FPS_SMEM>>>(xyz, out);
    ball_kernel<<<dim3(Sn/8, Bn), 256, BALL_SMEM>>>(xyz);
    build_pt<<<(Bn*Nn)/256, 256>>>(xyz, pts);

    // layer 1: gather-conv, pre-act -> g_A1, stats
    conv1_kernel<<<Pn/256, 256>>>(W0, b0);
    reduce_stats_kernel<<<64, 256>>>(Pn/256, 64, 0, g0, be0);

    // layer 2: staged conv (BN1+ReLU applied once at staging), pre-act -> g_A2
    convN_kernel<64,1,false><<<Pn/256, 256, CONV2_SMEM>>>(pA1, W1, b1, pA2);
    reduce_stats_kernel<<<64, 256>>>(Pn/256, 64, 1, g1, be1);

    // layer 3: staged conv + k-max of pre-act -> g_M, stats
    convN_kernel<128,2,true><<<Pn/128, 256, CONV3_SMEM>>>(pA2, W2, b2, nullptr);
    reduce_stats_kernel<<<128, 256>>>(Pn/128, 128, 2, g2, be2);

    // BN3 + ReLU on pooled maxima -> output
    finalize_kernel<<<(128*Sg)/256, 256>>>(outpts);
}

// round 14
// speedup vs baseline: 2.3468x; 1.0767x over previous
#include <cuda_runtime.h>
#include <cstdint>

#define Bn 16
#define Nn 4096
#define Sn 1024
#define Kn 32
#define Pn (Bn*Sn*Kn)   // 524288 positions
#define Sg (Bn*Sn)      // 16384 centroids
#define R2 0.01f

// ---------------- scratch ----------------
__device__ float g_newxyz[Bn*Sn*3];
__device__ int   g_ball[Bn*Sn*Kn];
__device__ float g_PT[(size_t)Bn*Nn*68];
__device__ float g_A1[(size_t)64*Pn];
__device__ float g_A2[(size_t)64*Pn];
__device__ float g_M [(size_t)128*Sg];
__device__ float g_p1[(size_t)8192*128];
__device__ float g_p2[(size_t)8192*128];
__device__ float g_scale[3][128];
__device__ float g_shift[3][128];

// ---------------- f32x2 helpers ----------------
union F2 { unsigned long long u; float2 f; };
typedef unsigned long long u64;

__device__ __forceinline__ u64 fma2(u64 a, u64 b, u64 c)
{
    u64 d;
    asm("fma.rn.f32x2 %0, %1, %2, %3;" : "=l"(d) : "l"(a), "l"(b), "l"(c));
    return d;
}
__device__ __forceinline__ u64 pack2(float x, float y)
{
    u64 r;
    asm("mov.b64 %0, {%1, %2};" : "=l"(r) : "r"(__float_as_uint(x)), "r"(__float_as_uint(y)));
    return r;
}
__device__ __forceinline__ u64 splat2(float x)
{
    u64 r;
    asm("mov.b64 %0, {%1, %1};" : "=l"(r) : "r"(__float_as_uint(x)));
    return r;
}

// ---------------- FPS (validated) ----------------
__global__ __launch_bounds__(256) void fps_kernel(const float* __restrict__ xyz,
                                                  float* __restrict__ out)
{
    extern __shared__ float sm[];
    float* sx = sm;
    float* sy = sm + Nn;
    float* sz = sm + 2*Nn;
    int*      sidx = (int*)(sm + 3*Nn);
    unsigned* rv   = (unsigned*)(sm + 3*Nn + Sn);
    unsigned* ri   = rv + 16;

    int b = blockIdx.x, t = threadIdx.x;
    int lane = t & 31, w = t >> 5;
    const float* xb = xyz + (size_t)b*3*Nn;
    for (int i = t; i < Nn; i += 256) {
        sx[i] = xb[i]; sy[i] = xb[Nn+i]; sz[i] = xb[2*Nn+i];
    }
    __syncthreads();

    float px[16], py[16], pz[16], dm[16];
#pragma unroll
    for (int j = 0; j < 16; j++) {
        int n = t + j*256;
        px[j]=sx[n]; py[j]=sy[n]; pz[j]=sz[n]; dm[j]=1e10f;
    }
    if (t == 0) sidx[0] = 0;
    int fcur = 0;

    for (int it = 1; it < Sn; it++) {
        float cx = sx[fcur], cy = sy[fcur], cz = sz[fcur];
        float bv = -1.f; int bi = 0;
#pragma unroll
        for (int j = 0; j < 16; j++) {
            float dx = __fadd_rn(px[j], -cx);
            float dy = __fadd_rn(py[j], -cy);
            float dz = __fadd_rn(pz[j], -cz);
            float d  = __fadd_rn(__fadd_rn(__fmul_rn(dx,dx), __fmul_rn(dy,dy)), __fmul_rn(dz,dz));
            float nd = fminf(dm[j], d);
            dm[j] = nd;
            if (nd > bv) { bv = nd; bi = t + j*256; }
        }
        unsigned vb   = __float_as_uint(bv);
        unsigned wmax = __reduce_max_sync(0xffffffffu, vb);
        unsigned cand = (vb == wmax) ? (unsigned)bi : 0xffffffffu;
        unsigned widx = __reduce_min_sync(0xffffffffu, cand);
        int pb = (it & 1) * 8;
        if (lane == 0) { rv[pb + w] = wmax; ri[pb + w] = widx; }
        __syncthreads();
        unsigned pv = (lane < 8) ? rv[pb + lane] : 0u;
        unsigned pi = (lane < 8) ? ri[pb + lane] : 0xffffffffu;
        unsigned gmax = __reduce_max_sync(0xffffffffu, pv);
        unsigned c2 = (lane < 8 && pv == gmax) ? pi : 0xffffffffu;
        fcur = (int)__reduce_min_sync(0xffffffffu, c2);
        if (t == 0) sidx[it] = fcur;
    }
    __syncthreads();

    for (int s = t; s < Sn; s += 256) {
        int n = sidx[s];
        float x = sx[n], y = sy[n], z = sz[n];
        g_newxyz[(b*Sn+s)*3+0] = x;
        g_newxyz[(b*Sn+s)*3+1] = y;
        g_newxyz[(b*Sn+s)*3+2] = z;
        out[((size_t)b*3+0)*Sn + s] = x;
        out[((size_t)b*3+1)*Sn + s] = y;
        out[((size_t)b*3+2)*Sn + s] = z;
    }
}

// ---------------- ball query ----------------
__global__ void ball_kernel(const float* __restrict__ xyz)
{
    extern __shared__ float bsm[];
    float* sx = bsm;
    float* sy = bsm + Nn;
    float* sz = bsm + 2*Nn;
    float* sn = bsm + 3*Nn;

    int b = blockIdx.y, t = threadIdx.x;
    const float* xb = xyz + (size_t)b*3*Nn;
    for (int i = t; i < Nn; i += 256) {
        float x = xb[i], y = xb[Nn+i], z = xb[2*Nn+i];
        sx[i]=x; sy[i]=y; sz[i]=z;
        sn[i] = __fadd_rn(__fadd_rn(__fmul_rn(x,x), __fmul_rn(y,y)), __fmul_rn(z,z));
    }
    __syncthreads();

    int w = t >> 5, lane = t & 31;
    int s = blockIdx.x*8 + w;
    const float* ctr = &g_newxyz[(b*Sn+s)*3];
    float cx = ctr[0], cy = ctr[1], cz = ctr[2];
    float cn = __fadd_rn(__fadd_rn(__fmul_rn(cx,cx), __fmul_rn(cy,cy)), __fmul_rn(cz,cz));

    int* dst = &g_ball[((size_t)b*Sn+s)*Kn];
    int cnt = 0, first = -1;
    for (int j = 0; j < Nn/32; j++) {
        int n = j*32 + lane;
        float dot = __fadd_rn(__fadd_rn(__fmul_rn(sx[n],cx), __fmul_rn(sy[n],cy)), __fmul_rn(sz[n],cz));
        float d = __fadd_rn(__fadd_rn(__fmul_rn(-2.f,dot), cn), sn[n]);
        bool in = !(d > R2);
        unsigned m = __ballot_sync(0xffffffffu, in);
        if (m) {
            if (first < 0) first = j*32 + __ffs(m) - 1;
            if (in) {
                int pos = cnt + __popc(m & ((1u<<lane)-1u));
                if (pos < Kn) dst[pos] = n;
            }
            cnt += __popc(m);
            if (cnt >= Kn) break;
        }
    }
    for (int pos = cnt + lane; pos < Kn; pos += 32) dst[pos] = first;
}

// ---------------- point table transpose ----------------
__global__ void build_pt(const float* __restrict__ xyz, const float* __restrict__ pts)
{
    int i = blockIdx.x*256 + threadIdx.x;
    int b = i >> 12, n = i & 4095;
    float* dst = &g_PT[(size_t)i*68];
    dst[0] = xyz[((size_t)b*3+0)*Nn + n];
    dst[1] = xyz[((size_t)b*3+1)*Nn + n];
    dst[2] = xyz[((size_t)b*3+2)*Nn + n];
#pragma unroll 4
    for (int c = 0; c < 64; c++) dst[3+c] = pts[((size_t)b*64+c)*Nn + n];
    dst[67] = 0.f;
}

// ---------------- per-subgroup stats output (no smem, no barrier) ----------------
template<int PL, int COUT>
__device__ __forceinline__ void stats_out(float (&s1)[8], float (&s2)[8],
                                          int co0, int nbIdx)
{
    int t = threadIdx.x;
#pragma unroll
    for (int j = 0; j < 8; j++) {
        float a = s1[j], bb = s2[j];
#pragma unroll
        for (int o = PL/2; o; o >>= 1) {
            a  += __shfl_down_sync(0xffffffffu, a,  o);
            bb += __shfl_down_sync(0xffffffffu, bb, o);
        }
        if ((t % PL) == 0) {
            g_p1[(size_t)nbIdx*COUT + co0 + j] = a;
            g_p2[(size_t)nbIdx*COUT + co0 + j] = bb;
        }
    }
}

// ---------------- layer 1: gather staged through smem, pure-fma2 inner ----------------
// Stage: each thread gathers one position's 68-float row (17 x LDG.128) and
// transposes it into tile[c][256] (consecutive lanes -> consecutive pos:
// conflict-free). Inner loop = convN pattern: u64 activation pairs + splatted
// weights, zero ALU packs. Center fold stays in acc init. c=67 pad skipped
// (weight 0 -> bit-identical).
__global__ __launch_bounds__(256, 2) void conv1_kernel(const float* __restrict__ W0,
                                                       const float* __restrict__ b0)
{
    extern __shared__ char dyn[];
    u64*   Wd   = (u64*)dyn;                        // [68][64] splatted {w,w}
    float* tile = (float*)(dyn + 68*64*8);          // [68][256]

    int t = threadIdx.x;
    for (int i = t; i < 68*64; i += 256) {
        int c = i >> 6, j = i & 63;
        float w = (c < 67) ? W0[j*67 + c] : 0.f;
        Wd[i] = splat2(w);
    }
    // gather + transpose stage
    {
        int p = blockIdx.x*256 + t;
        int b = p >> 15;
        int n = g_ball[p];
        const float4* row = (const float4*)&g_PT[((size_t)(b<<12) + (size_t)n)*68];
#pragma unroll
        for (int cc = 0; cc < 17; cc++) {
            float4 v = row[cc];
            tile[(cc*4+0)*256 + t] = v.x;
            tile[(cc*4+1)*256 + t] = v.y;
            tile[(cc*4+2)*256 + t] = v.z;
            tile[(cc*4+3)*256 + t] = v.w;
        }
    }
    __syncthreads();

    int grp = t >> 5, pl = t & 31, co0 = grp*8;
    int p0 = blockIdx.x*256 + pl*8;
    int sg = p0 >> 5;                    // 8 positions share one centroid
    float cx = g_newxyz[sg*3], cy = g_newxyz[sg*3+1], cz = g_newxyz[sg*3+2];

    F2 acc[32];                          // [j][pair p]: j*4+p
#pragma unroll
    for (int j = 0; j < 8; j++) {
        int jg = co0 + j;
        float w0x = W0[jg*67+0], w0y = W0[jg*67+1], w0z = W0[jg*67+2];
        float base = b0[jg] - (w0x*cx + w0y*cy + w0z*cz);
        u64 b2v = pack2(base, base);
#pragma unroll
        for (int p = 0; p < 4; p++) acc[j*4+p].u = b2v;
    }

#pragma unroll 4
    for (int c = 0; c < 67; c++) {
        const ulonglong2* xp = (const ulonglong2*)&tile[c*256 + pl*8];
        ulonglong2 q0 = xp[0], q1 = xp[1];
        u64 x[4] = {q0.x, q0.y, q1.x, q1.y};
        const ulonglong2* wp = (const ulonglong2*)&Wd[c*64 + co0];
        ulonglong2 wq0 = wp[0], wq1 = wp[1], wq2 = wp[2], wq3 = wp[3];
        u64 wv[8] = {wq0.x, wq0.y, wq1.x, wq1.y, wq2.x, wq2.y, wq3.x, wq3.y};
#pragma unroll
        for (int j = 0; j < 8; j++)
#pragma unroll
            for (int p = 0; p < 4; p++)
                acc[j*4+p].u = fma2(x[p], wv[j], acc[j*4+p].u);
    }

    float s1[8], s2[8];
#pragma unroll
    for (int j = 0; j < 8; j++) {
        float a0 = acc[j*4+0].f.x, a1 = acc[j*4+0].f.y;
        float a2 = acc[j*4+1].f.x, a3 = acc[j*4+1].f.y;
        float a4 = acc[j*4+2].f.x, a5 = acc[j*4+2].f.y;
        float a6 = acc[j*4+3].f.x, a7 = acc[j*4+3].f.y;
        float* dst = &g_A1[(size_t)(co0+j)*Pn + p0];
        *(float4*)dst       = make_float4(a0,a1,a2,a3);
        *(float4*)(dst + 4) = make_float4(a4,a5,a6,a7);
        s1[j] = (a0+a1+a2+a3) + (a4+a5+a6+a7);
        s2[j] = (a0*a0+a1*a1+a2*a2+a3*a3) + (a4*a4+a5*a5+a6*a6+a7*a7);
    }
    stats_out<32,64>(s1, s2, co0, blockIdx.x);
}

// ---------------- layers 2/3: smem-staged conv (pure fma2 inner) ----------------
template<int COUT, int LAYER, bool POOL>
__global__ __launch_bounds__(256, 2) void convN_kernel(const float* __restrict__ A,
                                                       const float* __restrict__ Wg,
                                                       const float* __restrict__ bg,
                                                       float* __restrict__ Aout)
{
    constexpr int CIN = 64;
    constexpr int G   = COUT / 8;          // 8 or 16
    constexpr int PL  = 256 / G;           // 32 or 16
    constexpr int PPB = PL * 8;            // 256 or 128

    extern __shared__ char dyn[];
    u64*   Wd   = (u64*)dyn;                            // CIN*COUT splatted
    float* tile = (float*)(dyn + (size_t)CIN*COUT*8);   // [c][PPB]
    __shared__ float sc[CIN], sh[CIN];

    int t = threadIdx.x;
    if (t < CIN) { sc[t] = g_scale[LAYER-1][t]; sh[t] = g_shift[LAYER-1][t]; }
    for (int i = t; i < CIN*COUT; i += 256) {
        int c = i / COUT, j = i % COUT;
        Wd[i] = splat2(Wg[j*CIN + c]);
    }
    __syncthreads();

    // stage activations with BN+ReLU applied once
    size_t base = (size_t)blockIdx.x * PPB;
    constexpr int F4R = PPB/4;
#pragma unroll 4
    for (int k = t; k < CIN*F4R; k += 256) {
        int c = k / F4R, off = (k % F4R)*4;
        float4 v = *(const float4*)&A[(size_t)c*Pn + base + off];
        float s = sc[c], h = sh[c];
        v.x = fmaxf(fmaf(v.x, s, h), 0.f);
        v.y = fmaxf(fmaf(v.y, s, h), 0.f);
        v.z = fmaxf(fmaf(v.z, s, h), 0.f);
        v.w = fmaxf(fmaf(v.w, s, h), 0.f);
        *(float4*)&tile[c*PPB + off] = v;
    }
    __syncthreads();

    int grp = t / PL, pl = t % PL, co0 = grp*8;
    int p0 = blockIdx.x*PPB + pl*8;

    F2 acc[32];
#pragma unroll
    for (int j = 0; j < 8; j++) {
        u64 b2v = pack2(bg[co0+j], bg[co0+j]);
#pragma unroll
        for (int p = 0; p < 4; p++) acc[j*4+p].u = b2v;
    }

#pragma unroll 4
    for (int c = 0; c < CIN; c++) {
        const ulonglong2* xp = (const ulonglong2*)&tile[c*PPB + pl*8];
        ulonglong2 q0 = xp[0], q1 = xp[1];
        u64 x[4] = {q0.x, q0.y, q1.x, q1.y};
        const ulonglong2* wp = (const ulonglong2*)&Wd[c*COUT + co0];
        ulonglong2 wq0 = wp[0], wq1 = wp[1], wq2 = wp[2], wq3 = wp[3];
        u64 wv[8] = {wq0.x, wq0.y, wq1.x, wq1.y, wq2.x, wq2.y, wq3.x, wq3.y};
#pragma unroll
        for (int j = 0; j < 8; j++)
#pragma unroll
            for (int p = 0; p < 4; p++)
                acc[j*4+p].u = fma2(x[p], wv[j], acc[j*4+p].u);
    }

    float s1[8], s2[8];
#pragma unroll
    for (int j = 0; j < 8; j++) {
        float a0 = acc[j*4+0].f.x, a1 = acc[j*4+0].f.y;
        float a2 = acc[j*4+1].f.x, a3 = acc[j*4+1].f.y;
        float a4 = acc[j*4+2].f.x, a5 = acc[j*4+2].f.y;
        float a6 = acc[j*4+3].f.x, a7 = acc[j*4+3].f.y;
        s1[j] = (a0+a1+a2+a3) + (a4+a5+a6+a7);
        s2[j] = (a0*a0+a1*a1+a2*a2+a3*a3) + (a4*a4+a5*a5+a6*a6+a7*a7);
        if (!POOL) {
            float* dst = &Aout[(size_t)(co0+j)*Pn + p0];
            *(float4*)dst       = make_float4(a0,a1,a2,a3);
            *(float4*)(dst + 4) = make_float4(a4,a5,a6,a7);
        }
    }
    if (POOL) {
        // 4 consecutive lanes share one centroid (4 lanes x 8 pos = 32 k).
        int sgG = p0 >> 5;
#pragma unroll
        for (int j = 0; j < 8; j++) {
            float m = fmaxf(fmaxf(fmaxf(acc[j*4+0].f.x, acc[j*4+0].f.y),
                                  fmaxf(acc[j*4+1].f.x, acc[j*4+1].f.y)),
                            fmaxf(fmaxf(acc[j*4+2].f.x, acc[j*4+2].f.y),
                                  fmaxf(acc[j*4+3].f.x, acc[j*4+3].f.y)));
            m = fmaxf(m, __shfl_xor_sync(0xffffffffu, m, 1));
            m = fmaxf(m, __shfl_xor_sync(0xffffffffu, m, 2));
            if ((pl & 3) == (j & 3))
                g_M[(size_t)(co0+j)*Sg + sgG] = m;
        }
    }
    stats_out<PL,COUT>(s1, s2, co0, blockIdx.x);
}

// ---------------- stats -> scale/shift ----------------
__global__ void reduce_stats_kernel(int NB, int COUT, int layer,
                                    const float* __restrict__ gamma,
                                    const float* __restrict__ beta)
{
    int co = blockIdx.x, t = threadIdx.x;
    double s1 = 0.0, s2 = 0.0;
    for (int i = t; i < NB; i += 256) {
        s1 += (double)g_p1[(size_t)i*COUT + co];
        s2 += (double)g_p2[(size_t)i*COUT + co];
    }
    __shared__ double r1[256], r2[256];
    r1[t] = s1; r2[t] = s2;
    __syncthreads();
    for (int o = 128; o; o >>= 1) {
        if (t < o) { r1[t] += r1[t+o]; r2[t] += r2[t+o]; }
        __syncthreads();
    }
    if (t == 0) {
        double mu  = r1[0] * (1.0 / Pn);
        double var = r2[0] * (1.0 / Pn) - mu*mu;
        double scd = (double)gamma[co] / sqrt(var + 1e-5);
        g_scale[layer][co] = (float)scd;
        g_shift[layer][co] = (float)((double)beta[co] - mu*scd);
    }
}

// ---------------- finalize: BN3+ReLU on pooled pre-act max ----------------
__global__ void finalize_kernel(float* __restrict__ outpts)
{
    int i = blockIdx.x*256 + threadIdx.x;
    int co = i >> 14, sg = i & 16383;
    float y = fmaf(g_M[i], g_scale[2][co], g_shift[2][co]);
    y = fmaxf(y, 0.f);
    int b = sg >> 10, s = sg & 1023;
    outpts[((size_t)(b*128 + co))*1024 + s] = y;
}

// ---------------- launch ----------------
extern "C" void kernel_launch(void* const* d_in, const int* in_sizes, int n_in,
                              void* d_out, int out_size)
{
    const float* xyz = (const float*)d_in[0];
    const float* pts = (const float*)d_in[1];
    const float* W0  = (const float*)d_in[2];
    const float* b0  = (const float*)d_in[3];
    const float* g0  = (const float*)d_in[4];
    const float* be0 = (const float*)d_in[5];
    const float* W1  = (const float*)d_in[6];
    const float* b1  = (const float*)d_in[7];
    const float* g1  = (const float*)d_in[8];
    const float* be1 = (const float*)d_in[9];
    const float* W2  = (const float*)d_in[10];
    const float* b2  = (const float*)d_in[11];
    const float* g2  = (const float*)d_in[12];
    const float* be2 = (const float*)d_in[13];

    float* out    = (float*)d_out;
    float* outpts = out + (size_t)Bn*3*Sn;

    const int FPS_SMEM  = (3*Nn + Sn + 32) * 4 + 256;
    const int BALL_SMEM = 4*Nn*4;
    // conv1: W 68*64*8=34816 + tile 68*256*4=69632 -> 104448 B
    // conv2: W 64*64*8=32KB + tile 64*256*4=64KB = 96KB
    // conv3: W 64*128*8=64KB + tile 64*128*4=32KB = 96KB
    const int CONV1_SMEM = 68*64*8 + 68*256*4;
    const int CONV2_SMEM = 64*64*8 + 64*256*4;
    const int CONV3_SMEM = 64*128*8 + 64*128*4;
    cudaFuncSetAttribute(fps_kernel,  cudaFuncAttributeMaxDynamicSharedMemorySize, FPS_SMEM);
    cudaFuncSetAttribute(ball_kernel, cudaFuncAttributeMaxDynamicSharedMemorySize, BALL_SMEM);
    cudaFuncSetAttribute(conv1_kernel,
                         cudaFuncAttributeMaxDynamicSharedMemorySize, CONV1_SMEM);
    cudaFuncSetAttribute(convN_kernel<64,1,false>,
                         cudaFuncAttributeMaxDynamicSharedMemorySize, CONV2_SMEM);
    cudaFuncSetAttribute(convN_kernel<128,2,true>,
                         cudaFuncAttributeMaxDynamicSharedMemorySize, CONV3_SMEM);

    float *pA1 = nullptr, *pA2 = nullptr;
    cudaGetSymbolAddress((void**)&pA1, g_A1);
    cudaGetSymbolAddress((void**)&pA2, g_A2);

    fps_kernel<<<Bn, 256, FPS_SMEM>>>(xyz, out);
    ball_kernel<<<dim3(Sn/8, Bn), 256, BALL_SMEM>>>(xyz);
    build_pt<<<(Bn*Nn)/256, 256>>>(xyz, pts);

    // layer 1: staged gather-conv, pre-act -> g_A1, stats
    conv1_kernel<<<Pn/256, 256, CONV1_SMEM>>>(W0, b0);
    reduce_stats_kernel<<<64, 256>>>(Pn/256, 64, 0, g0, be0);

    // layer 2: staged conv (BN1+ReLU applied once at staging), pre-act -> g_A2
    convN_kernel<64,1,false><<<Pn/256, 256, CONV2_SMEM>>>(pA1, W1, b1, pA2);
    reduce_stats_kernel<<<64, 256>>>(Pn/256, 64, 1, g1, be1);

    // layer 3: staged conv + k-max of pre-act -> g_M, stats
    convN_kernel<128,2,true><<<Pn/128, 256, CONV3_SMEM>>>(pA2, W2, b2, nullptr);
    reduce_stats_kernel<<<128, 256>>>(Pn/128, 128, 2, g2, be2);

    // BN3 + ReLU on pooled maxima -> output
    finalize_kernel<<<(128*Sg)/256, 256>>>(outpts);
}

// round 15
// speedup vs baseline: 2.7946x; 1.1908x over previous
#include <cuda_runtime.h>
#include <cstdint>

#define Bn 16
#define Nn 4096
#define Sn 1024
#define Kn 32
#define Pn (Bn*Sn*Kn)   // 524288 positions
#define Sg (Bn*Sn)      // 16384 centroids
#define NT (Bn*Nn)      // 65536 points
#define R2 0.01f

// ---------------- scratch ----------------
__device__ float g_newxyz[Bn*Sn*3];
__device__ int   g_ball[Bn*Sn*Kn];
__device__ float g_U[(size_t)NT*64];     // layer1 point-term table [n][64]
__device__ float g_V[(size_t)Sg*64];     // layer1 centroid-term  [s][64]
__device__ float g_A1[(size_t)64*Pn];
__device__ float g_A2[(size_t)64*Pn];
__device__ float g_M [(size_t)128*Sg];
__device__ float g_p1[(size_t)8192*128];
__device__ float g_p2[(size_t)8192*128];
__device__ float g_scale[3][128];
__device__ float g_shift[3][128];

// ---------------- f32x2 helpers ----------------
union F2 { unsigned long long u; float2 f; };
typedef unsigned long long u64;

__device__ __forceinline__ u64 fma2(u64 a, u64 b, u64 c)
{
    u64 d;
    asm("fma.rn.f32x2 %0, %1, %2, %3;" : "=l"(d) : "l"(a), "l"(b), "l"(c));
    return d;
}
__device__ __forceinline__ u64 add2(u64 a, u64 b)
{
    u64 d;
    asm("add.rn.f32x2 %0, %1, %2;" : "=l"(d) : "l"(a), "l"(b));
    return d;
}
__device__ __forceinline__ u64 mul2(u64 a, u64 b)
{
    u64 d;
    asm("mul.rn.f32x2 %0, %1, %2;" : "=l"(d) : "l"(a), "l"(b));
    return d;
}
__device__ __forceinline__ u64 pack2(float x, float y)
{
    u64 r;
    asm("mov.b64 %0, {%1, %2};" : "=l"(r) : "r"(__float_as_uint(x)), "r"(__float_as_uint(y)));
    return r;
}
__device__ __forceinline__ u64 splat2(float x)
{
    u64 r;
    asm("mov.b64 %0, {%1, %1};" : "=l"(r) : "r"(__float_as_uint(x)));
    return r;
}

// ---------------- FPS (f32x2 distance math, bit-identical per lane) ----------------
__global__ __launch_bounds__(256) void fps_kernel(const float* __restrict__ xyz,
                                                  float* __restrict__ out)
{
    extern __shared__ float sm[];
    float* sx = sm;
    float* sy = sm + Nn;
    float* sz = sm + 2*Nn;
    int*      sidx = (int*)(sm + 3*Nn);
    unsigned* rv   = (unsigned*)(sm + 3*Nn + Sn);
    unsigned* ri   = rv + 16;

    int b = blockIdx.x, t = threadIdx.x;
    int lane = t & 31, w = t >> 5;
    const float* xb = xyz + (size_t)b*3*Nn;
    for (int i = t; i < Nn; i += 256) {
        sx[i] = xb[i]; sy[i] = xb[Nn+i]; sz[i] = xb[2*Nn+i];
    }
    __syncthreads();

    // 16 points per thread as 8 f32x2 pairs: pair k = points (t+2k*256, t+(2k+1)*256)
    u64 px2[8], py2[8], pz2[8];
    float dm[16];
#pragma unroll
    for (int k = 0; k < 8; k++) {
        int n0 = t + (2*k)*256, n1 = t + (2*k+1)*256;
        px2[k] = pack2(sx[n0], sx[n1]);
        py2[k] = pack2(sy[n0], sy[n1]);
        pz2[k] = pack2(sz[n0], sz[n1]);
        dm[2*k] = 1e10f; dm[2*k+1] = 1e10f;
    }
    if (t == 0) sidx[0] = 0;
    int fcur = 0;

    for (int it = 1; it < Sn; it++) {
        u64 ncx = splat2(-sx[fcur]);
        u64 ncy = splat2(-sy[fcur]);
        u64 ncz = splat2(-sz[fcur]);
        float bv = -1.f; int bi = 0;
#pragma unroll
        for (int k = 0; k < 8; k++) {
            u64 dx = add2(px2[k], ncx);
            u64 dy = add2(py2[k], ncy);
            u64 dz = add2(pz2[k], ncz);
            F2 d; d.u = add2(add2(mul2(dx,dx), mul2(dy,dy)), mul2(dz,dz));
            float nd0 = fminf(dm[2*k],   d.f.x);
            float nd1 = fminf(dm[2*k+1], d.f.y);
            dm[2*k] = nd0; dm[2*k+1] = nd1;
            if (nd0 > bv) { bv = nd0; bi = t + (2*k)*256; }
            if (nd1 > bv) { bv = nd1; bi = t + (2*k+1)*256; }
        }
        unsigned vb   = __float_as_uint(bv);
        unsigned wmax = __reduce_max_sync(0xffffffffu, vb);
        unsigned cand = (vb == wmax) ? (unsigned)bi : 0xffffffffu;
        unsigned widx = __reduce_min_sync(0xffffffffu, cand);
        int pb = (it & 1) * 8;
        if (lane == 0) { rv[pb + w] = wmax; ri[pb + w] = widx; }
        __syncthreads();
        unsigned pv = (lane < 8) ? rv[pb + lane] : 0u;
        unsigned pi = (lane < 8) ? ri[pb + lane] : 0xffffffffu;
        unsigned gmax = __reduce_max_sync(0xffffffffu, pv);
        unsigned c2 = (lane < 8 && pv == gmax) ? pi : 0xffffffffu;
        fcur = (int)__reduce_min_sync(0xffffffffu, c2);
        if (t == 0) sidx[it] = fcur;
    }
    __syncthreads();

    for (int s = t; s < Sn; s += 256) {
        int n = sidx[s];
        float x = sx[n], y = sy[n], z = sz[n];
        g_newxyz[(b*Sn+s)*3+0] = x;
        g_newxyz[(b*Sn+s)*3+1] = y;
        g_newxyz[(b*Sn+s)*3+2] = z;
        out[((size_t)b*3+0)*Sn + s] = x;
        out[((size_t)b*3+1)*Sn + s] = y;
        out[((size_t)b*3+2)*Sn + s] = z;
    }
}

// ---------------- ball query ----------------
__global__ void ball_kernel(const float* __restrict__ xyz)
{
    extern __shared__ float bsm[];
    float* sx = bsm;
    float* sy = bsm + Nn;
    float* sz = bsm + 2*Nn;
    float* sn = bsm + 3*Nn;

    int b = blockIdx.y, t = threadIdx.x;
    const float* xb = xyz + (size_t)b*3*Nn;
    for (int i = t; i < Nn; i += 256) {
        float x = xb[i], y = xb[Nn+i], z = xb[2*Nn+i];
        sx[i]=x; sy[i]=y; sz[i]=z;
        sn[i] = __fadd_rn(__fadd_rn(__fmul_rn(x,x), __fmul_rn(y,y)), __fmul_rn(z,z));
    }
    __syncthreads();

    int w = t >> 5, lane = t & 31;
    int s = blockIdx.x*8 + w;
    const float* ctr = &g_newxyz[(b*Sn+s)*3];
    float cx = ctr[0], cy = ctr[1], cz = ctr[2];
    float cn = __fadd_rn(__fadd_rn(__fmul_rn(cx,cx), __fmul_rn(cy,cy)), __fmul_rn(cz,cz));

    int* dst = &g_ball[((size_t)b*Sn+s)*Kn];
    int cnt = 0, first = -1;
    for (int j = 0; j < Nn/32; j++) {
        int n = j*32 + lane;
        float dot = __fadd_rn(__fadd_rn(__fmul_rn(sx[n],cx), __fmul_rn(sy[n],cy)), __fmul_rn(sz[n],cz));
        float d = __fadd_rn(__fadd_rn(__fmul_rn(-2.f,dot), cn), sn[n]);
        bool in = !(d > R2);
        unsigned m = __ballot_sync(0xffffffffu, in);
        if (m) {
            if (first < 0) first = j*32 + __ffs(m) - 1;
            if (in) {
                int pos = cnt + __popc(m & ((1u<<lane)-1u));
                if (pos < Kn) dst[pos] = n;
            }
            cnt += __popc(m);
            if (cnt >= Kn) break;
        }
    }
    for (int pos = cnt + lane; pos < Kn; pos += 32) dst[pos] = first;
}

// ---------------- U table: U[n] = chain(b0 + W.[xyz, pts]) over c ascending ----------------
// thread = 1 point, 64 channels as 32 ch-pairs. tile[c][256] staged coalesced
// straight from xyz/pts (c-major native). Weights as {W[2j][c],W[2j+1][c]} pairs.
__global__ __launch_bounds__(256, 2) void u_kernel(const float* __restrict__ xyz,
                                                   const float* __restrict__ pts,
                                                   const float* __restrict__ W0,
                                                   const float* __restrict__ b0)
{
    extern __shared__ char dyn[];
    u64*   Wp   = (u64*)dyn;                    // [67][32] ch-pair weights
    float* tile = (float*)(dyn + 67*32*8);      // [67][256]

    int t = threadIdx.x;
    for (int i = t; i < 67*32; i += 256) {
        int c = i >> 5, jp = i & 31;
        Wp[i] = pack2(W0[(2*jp)*67 + c], W0[(2*jp+1)*67 + c]);
    }
    // stage: block covers 256 consecutive points within one batch
    int pbase = blockIdx.x * 256;          // global point id base
    int b = pbase >> 12;
    int nb = pbase & 4095;                 // within-batch offset
    for (int k = t; k < 67*64; k += 256) {
        int c = k >> 6, f4 = k & 63;
        const float* src = (c < 3)
            ? &xyz[((size_t)b*3 + c)*Nn + nb]
            : &pts[((size_t)b*64 + (c-3))*Nn + nb];
        *(float4*)&tile[c*256 + f4*4] = *(const float4*)&src[f4*4];
    }
    __syncthreads();

    F2 acc[32];
#pragma unroll
    for (int jp = 0; jp < 32; jp++) acc[jp].u = pack2(b0[2*jp], b0[2*jp+1]);

#pragma unroll 4
    for (int c = 0; c < 67; c++) {
        u64 x = splat2(tile[c*256 + t]);
        const ulonglong2* wp = (const ulonglong2*)&Wp[c*32];
#pragma unroll
        for (int m = 0; m < 16; m++) {
            ulonglong2 wq = wp[m];
            acc[2*m  ].u = fma2(x, wq.x, acc[2*m  ].u);
            acc[2*m+1].u = fma2(x, wq.y, acc[2*m+1].u);
        }
    }

    float* dst = &g_U[(size_t)(pbase + t)*64];
#pragma unroll
    for (int m = 0; m < 16; m++) {
        ulonglong2 v; v.x = acc[2*m].u; v.y = acc[2*m+1].u;
        *(ulonglong2*)&dst[m*4] = v;
    }
}

// ---------------- V table: V[s][j] = W[j,:3] . c_s ----------------
__global__ void v_kernel(const float* __restrict__ W0)
{
    int i = blockIdx.x*256 + threadIdx.x;      // Sg*64
    int s = i >> 6, j = i & 63;
    float cx = g_newxyz[s*3], cy = g_newxyz[s*3+1], cz = g_newxyz[s*3+2];
    g_V[i] = W0[j*67+0]*cx + W0[j*67+1]*cy + W0[j*67+2]*cz;
}

// ---------------- per-subgroup stats output ----------------
template<int PL, int COUT>
__device__ __forceinline__ void stats_out(float (&s1)[8], float (&s2)[8],
                                          int co0, int nbIdx)
{
    int t = threadIdx.x;
#pragma unroll
    for (int j = 0; j < 8; j++) {
        float a = s1[j], bb = s2[j];
#pragma unroll
        for (int o = PL/2; o; o >>= 1) {
            a  += __shfl_down_sync(0xffffffffu, a,  o);
            bb += __shfl_down_sync(0xffffffffu, bb, o);
        }
        if ((t % PL) == 0) {
            g_p1[(size_t)nbIdx*COUT + co0 + j] = a;
            g_p2[(size_t)nbIdx*COUT + co0 + j] = bb;
        }
    }
}

// ---------------- layer-1 assembly: A1[c][p] = U[n_p][c] - V[s_p][c], + stats ----------------
__global__ __launch_bounds__(256, 2) void gather1_kernel()
{
    extern __shared__ char dyn[];
    float* tile = (float*)dyn;                  // [64][256]

    int t = threadIdx.x;
    // stage: gather U row of this thread's position, transpose into tile
    {
        int p = blockIdx.x*256 + t;
        int b = p >> 15;
        int n = g_ball[p];
        const float4* row = (const float4*)&g_U[(size_t)((b<<12) + n)*64];
#pragma unroll
        for (int m = 0; m < 16; m++) {
            float4 v = row[m];
            tile[(m*4+0)*256 + t] = v.x;
            tile[(m*4+1)*256 + t] = v.y;
            tile[(m*4+2)*256 + t] = v.z;
            tile[(m*4+3)*256 + t] = v.w;
        }
    }
    __syncthreads();

    int grp = t >> 5, pl = t & 31, co0 = grp*8;
    int p0 = blockIdx.x*256 + pl*8;
    int sg = p0 >> 5;
    const float* vrow = &g_V[(size_t)sg*64 + co0];

    float s1[8], s2[8];
#pragma unroll
    for (int j = 0; j < 8; j++) {
        u64 nv = splat2(-vrow[j]);
        const ulonglong2* xp = (const ulonglong2*)&tile[(co0+j)*256 + pl*8];
        ulonglong2 q0 = xp[0], q1 = xp[1];
        F2 r0, r1, r2, r3;
        r0.u = add2(q0.x, nv); r1.u = add2(q0.y, nv);
        r2.u = add2(q1.x, nv); r3.u = add2(q1.y, nv);
        float a0 = r0.f.x, a1 = r0.f.y, a2 = r1.f.x, a3 = r1.f.y;
        float a4 = r2.f.x, a5 = r2.f.y, a6 = r3.f.x, a7 = r3.f.y;
        float* dst = &g_A1[(size_t)(co0+j)*Pn + p0];
        *(float4*)dst       = make_float4(a0,a1,a2,a3);
        *(float4*)(dst + 4) = make_float4(a4,a5,a6,a7);
        s1[j] = (a0+a1+a2+a3) + (a4+a5+a6+a7);
        s2[j] = (a0*a0+a1*a1+a2*a2+a3*a3) + (a4*a4+a5*a5+a6*a6+a7*a7);
    }
    stats_out<32,64>(s1, s2, co0, blockIdx.x);
}

// ---------------- layers 2/3: smem-staged conv (pure fma2 inner) ----------------
template<int COUT, int LAYER, bool POOL>
__global__ __launch_bounds__(256, 2) void convN_kernel(const float* __restrict__ A,
                                                       const float* __restrict__ Wg,
                                                       const float* __restrict__ bg,
                                                       float* __restrict__ Aout)
{
    constexpr int CIN = 64;
    constexpr int G   = COUT / 8;
    constexpr int PL  = 256 / G;
    constexpr int PPB = PL * 8;

    extern __shared__ char dyn[];
    u64*   Wd   = (u64*)dyn;
    float* tile = (float*)(dyn + (size_t)CIN*COUT*8);
    __shared__ float sc[CIN], sh[CIN];

    int t = threadIdx.x;
    if (t < CIN) { sc[t] = g_scale[LAYER-1][t]; sh[t] = g_shift[LAYER-1][t]; }
    for (int i = t; i < CIN*COUT; i += 256) {
        int c = i / COUT, j = i % COUT;
        Wd[i] = splat2(Wg[j*CIN + c]);
    }
    __syncthreads();

    size_t base = (size_t)blockIdx.x * PPB;
    constexpr int F4R = PPB/4;
#pragma unroll 4
    for (int k = t; k < CIN*F4R; k += 256) {
        int c = k / F4R, off = (k % F4R)*4;
        float4 v = *(const float4*)&A[(size_t)c*Pn + base + off];
        float s = sc[c], h = sh[c];
        v.x = fmaxf(fmaf(v.x, s, h), 0.f);
        v.y = fmaxf(fmaf(v.y, s, h), 0.f);
        v.z = fmaxf(fmaf(v.z, s, h), 0.f);
        v.w = fmaxf(fmaf(v.w, s, h), 0.f);
        *(float4*)&tile[c*PPB + off] = v;
    }
    __syncthreads();

    int grp = t / PL, pl = t % PL, co0 = grp*8;
    int p0 = blockIdx.x*PPB + pl*8;

    F2 acc[32];
#pragma unroll
    for (int j = 0; j < 8; j++) {
        u64 b2v = pack2(bg[co0+j], bg[co0+j]);
#pragma unroll
        for (int p = 0; p < 4; p++) acc[j*4+p].u = b2v;
    }

#pragma unroll 4
    for (int c = 0; c < CIN; c++) {
        const ulonglong2* xp = (const ulonglong2*)&tile[c*PPB + pl*8];
        ulonglong2 q0 = xp[0], q1 = xp[1];
        u64 x[4] = {q0.x, q0.y, q1.x, q1.y};
        const ulonglong2* wp = (const ulonglong2*)&Wd[c*COUT + co0];
        ulonglong2 wq0 = wp[0], wq1 = wp[1], wq2 = wp[2], wq3 = wp[3];
        u64 wv[8] = {wq0.x, wq0.y, wq1.x, wq1.y, wq2.x, wq2.y, wq3.x, wq3.y};
#pragma unroll
        for (int j = 0; j < 8; j++)
#pragma unroll
            for (int p = 0; p < 4; p++)
                acc[j*4+p].u = fma2(x[p], wv[j], acc[j*4+p].u);
    }

    float s1[8], s2[8];
#pragma unroll
    for (int j = 0; j < 8; j++) {
        float a0 = acc[j*4+0].f.x, a1 = acc[j*4+0].f.y;
        float a2 = acc[j*4+1].f.x, a3 = acc[j*4+1].f.y;
        float a4 = acc[j*4+2].f.x, a5 = acc[j*4+2].f.y;
        float a6 = acc[j*4+3].f.x, a7 = acc[j*4+3].f.y;
        s1[j] = (a0+a1+a2+a3) + (a4+a5+a6+a7);
        s2[j] = (a0*a0+a1*a1+a2*a2+a3*a3) + (a4*a4+a5*a5+a6*a6+a7*a7);
        if (!POOL) {
            float* dst = &Aout[(size_t)(co0+j)*Pn + p0];
            *(float4*)dst       = make_float4(a0,a1,a2,a3);
            *(float4*)(dst + 4) = make_float4(a4,a5,a6,a7);
        }
    }
    if (POOL) {
        int sgG = p0 >> 5;
#pragma unroll
        for (int j = 0; j < 8; j++) {
            float m = fmaxf(fmaxf(fmaxf(acc[j*4+0].f.x, acc[j*4+0].f.y),
                                  fmaxf(acc[j*4+1].f.x, acc[j*4+1].f.y)),
                            fmaxf(fmaxf(acc[j*4+2].f.x, acc[j*4+2].f.y),
                                  fmaxf(acc[j*4+3].f.x, acc[j*4+3].f.y)));
            m = fmaxf(m, __shfl_xor_sync(0xffffffffu, m, 1));
            m = fmaxf(m, __shfl_xor_sync(0xffffffffu, m, 2));
            if ((pl & 3) == (j & 3))
                g_M[(size_t)(co0+j)*Sg + sgG] = m;
        }
    }
    stats_out<PL,COUT>(s1, s2, co0, blockIdx.x);
}

// ---------------- stats -> scale/shift ----------------
__global__ void reduce_stats_kernel(int NB, int COUT, int layer,
                                    const float* __restrict__ gamma,
                                    const float* __restrict__ beta)
{
    int co = blockIdx.x, t = threadIdx.x;
    double s1 = 0.0, s2 = 0.0;
    for (int i = t; i < NB; i += 256) {
        s1 += (double)g_p1[(size_t)i*COUT + co];
        s2 += (double)g_p2[(size_t)i*COUT + co];
    }
    __shared__ double r1[256], r2[256];
    r1[t] = s1; r2[t] = s2;
    __syncthreads();
    for (int o = 128; o; o >>= 1) {
        if (t < o) { r1[t] += r1[t+o]; r2[t] += r2[t+o]; }
        __syncthreads();
    }
    if (t == 0) {
        double mu  = r1[0] * (1.0 / Pn);
        double var = r2[0] * (1.0 / Pn) - mu*mu;
        double scd = (double)gamma[co] / sqrt(var + 1e-5);
        g_scale[layer][co] = (float)scd;
        g_shift[layer][co] = (float)((double)beta[co] - mu*scd);
    }
}

// ---------------- finalize: BN3+ReLU on pooled pre-act max ----------------
__global__ void finalize_kernel(float* __restrict__ outpts)
{
    int i = blockIdx.x*256 + threadIdx.x;
    int co = i >> 14, sg = i & 16383;
    float y = fmaf(g_M[i], g_scale[2][co], g_shift[2][co]);
    y = fmaxf(y, 0.f);
    int b = sg >> 10, s = sg & 1023;
    outpts[((size_t)(b*128 + co))*1024 + s] = y;
}

// ---------------- launch ----------------
extern "C" void kernel_launch(void* const* d_in, const int* in_sizes, int n_in,
                              void* d_out, int out_size)
{
    const float* xyz = (const float*)d_in[0];
    const float* pts = (const float*)d_in[1];
    const float* W0  = (const float*)d_in[2];
    const float* b0  = (const float*)d_in[3];
    const float* g0  = (const float*)d_in[4];
    const float* be0 = (const float*)d_in[5];
    const float* W1  = (const float*)d_in[6];
    const float* b1  = (const float*)d_in[7];
    const float* g1  = (const float*)d_in[8];
    const float* be1 = (const float*)d_in[9];
    const float* W2  = (const float*)d_in[10];
    const float* b2  = (const float*)d_in[11];
    const float* g2  = (const float*)d_in[12];
    const float* be2 = (const float*)d_in[13];

    float* out    = (float*)d_out;
    float* outpts = out + (size_t)Bn*3*Sn;

    const int FPS_SMEM  = (3*Nn + Sn + 32) * 4 + 256;
    const int BALL_SMEM = 4*Nn*4;
    const int U_SMEM    = 67*32*8 + 67*256*4;   // 17152 + 68608 = 85760
    const int G1_SMEM   = 64*256*4;             // 64 KB
    const int CONV2_SMEM = 64*64*8 + 64*256*4;  // 96 KB
    const int CONV3_SMEM = 64*128*8 + 64*128*4; // 96 KB
    cudaFuncSetAttribute(fps_kernel,  cudaFuncAttributeMaxDynamicSharedMemorySize, FPS_SMEM);
    cudaFuncSetAttribute(ball_kernel, cudaFuncAttributeMaxDynamicSharedMemorySize, BALL_SMEM);
    cudaFuncSetAttribute(u_kernel,    cudaFuncAttributeMaxDynamicSharedMemorySize, U_SMEM);
    cudaFuncSetAttribute(gather1_kernel,
                         cudaFuncAttributeMaxDynamicSharedMemorySize, G1_SMEM);
    cudaFuncSetAttribute(convN_kernel<64,1,false>,
                         cudaFuncAttributeMaxDynamicSharedMemorySize, CONV2_SMEM);
    cudaFuncSetAttribute(convN_kernel<128,2,true>,
                         cudaFuncAttributeMaxDynamicSharedMemorySize, CONV3_SMEM);

    float *pA1 = nullptr, *pA2 = nullptr;
    cudaGetSymbolAddress((void**)&pA1, g_A1);
    cudaGetSymbolAddress((void**)&pA2, g_A2);

    // U table is FPS-independent; launch first.
    u_kernel<<<NT/256, 256, U_SMEM>>>(xyz, pts, W0, b0);
    fps_kernel<<<Bn, 256, FPS_SMEM>>>(xyz, out);
    ball_kernel<<<dim3(Sn/8, Bn), 256, BALL_SMEM>>>(xyz);
    v_kernel<<<(Sg*64)/256, 256>>>(W0);

    // layer 1 assembly: A1 = U[n] - V[s], stats
    gather1_kernel<<<Pn/256, 256, G1_SMEM>>>();
    reduce_stats_kernel<<<64, 256>>>(Pn/256, 64, 0, g0, be0);

    // layer 2
    convN_kernel<64,1,false><<<Pn/256, 256, CONV2_SMEM>>>(pA1, W1, b1, pA2);
    reduce_stats_kernel<<<64, 256>>>(Pn/256, 64, 1, g1, be1);

    // layer 3 + k-max pool
    convN_kernel<128,2,true><<<Pn/128, 256, CONV3_SMEM>>>(pA2, W2, b2, nullptr);
    reduce_stats_kernel<<<128, 256>>>(Pn/128, 128, 2, g2, be2);

    finalize_kernel<<<(128*Sg)/256, 256>>>(outpts);
}